// round 1
// baseline (speedup 1.0000x reference)
#include <cuda_runtime.h>

// Problem constants
#define NB   2
#define NS   2048
#define ND   512
#define NH   8
#define NQ   64
#define NHD  64
#define NBS  (NB*NS)            // 4096 tokens
#define QKV_ELEMS (NB*NH*NS*NHD) // 2,097,152

// Scratch (device globals; no allocations allowed)
__device__ float g_ge[3][2][NQ*NQ];      // folded gr@ent / gi@ent per projection
__device__ float g_qkv[3][QKV_ELEMS];    // scaled qs/ks/vs in (b,h,s,d)
__device__ float g_qm[QKV_ELEMS];        // qs @ interf[h], (b,h,s,d)
__device__ float g_ao[NBS*ND];           // attention out, (b,s,D)

// ---------------------------------------------------------------------------
// helpers: 64x64 tile loads into smem with row stride 65 (pad)
// ---------------------------------------------------------------------------
__device__ __forceinline__ void load_tile_strided(float* s, const float* g, int ldg, int tid) {
    // 64x64 tile, global row stride ldg (floats), 256 threads, float4 loads
#pragma unroll
    for (int i = 0; i < 4; i++) {
        int idx = tid + 256 * i;          // 0..1023 float4s
        int row = idx >> 4;               // 16 float4 per row
        int c   = (idx & 15) * 4;
        float4 v = *reinterpret_cast<const float4*>(g + (size_t)row * ldg + c);
        s[row*65 + c + 0] = v.x;
        s[row*65 + c + 1] = v.y;
        s[row*65 + c + 2] = v.z;
        s[row*65 + c + 3] = v.w;
    }
}

__device__ __forceinline__ void load_tile_contig(float* s, const float* g, int tid) {
    // 64x64 tile stored contiguously (4096 floats) in global
#pragma unroll
    for (int i = 0; i < 4; i++) {
        int idx = tid + 256 * i;
        float4 v = reinterpret_cast<const float4*>(g)[idx];
        int row = idx >> 4;
        int c   = (idx & 15) * 4;
        s[row*65 + c + 0] = v.x;
        s[row*65 + c + 1] = v.y;
        s[row*65 + c + 2] = v.z;
        s[row*65 + c + 3] = v.w;
    }
}

// C[64x64] += A[64x64] * B[64x64], A row-major, B row-major, 4x4 per thread
__device__ __forceinline__ void mm64(float acc[4][4], const float* A, const float* Bm, int ty, int tx) {
#pragma unroll 8
    for (int kk = 0; kk < 64; kk++) {
        float a[4], b[4];
#pragma unroll
        for (int i = 0; i < 4; i++) a[i] = A[(ty*4 + i)*65 + kk];
#pragma unroll
        for (int j = 0; j < 4; j++) b[j] = Bm[kk*65 + tx*4 + j];
#pragma unroll
        for (int i = 0; i < 4; i++)
#pragma unroll
            for (int j = 0; j < 4; j++)
                acc[i][j] = fmaf(a[i], b[j], acc[i][j]);
    }
}

// C[64x64] += A[64x64] * B^T  (B stored row-major [col][k]) — used for Q@K^T
__device__ __forceinline__ void mm64_bt(float acc[4][4], const float* A, const float* Bm, int ty, int tx) {
#pragma unroll 8
    for (int kk = 0; kk < 64; kk++) {
        float a[4], b[4];
#pragma unroll
        for (int i = 0; i < 4; i++) a[i] = A[(ty*4 + i)*65 + kk];
#pragma unroll
        for (int j = 0; j < 4; j++) b[j] = Bm[(tx*4 + j)*65 + kk];
#pragma unroll
        for (int i = 0; i < 4; i++)
#pragma unroll
            for (int j = 0; j < 4; j++)
                acc[i][j] = fmaf(a[i], b[j], acc[i][j]);
    }
}

// ---------------------------------------------------------------------------
// Kernel 1: fold gate matrices: gre = gr@ent, gie = gi@ent (3 projections)
// ---------------------------------------------------------------------------
__global__ void k_prep(const float* __restrict__ grq, const float* __restrict__ giq, const float* __restrict__ entq,
                       const float* __restrict__ grk, const float* __restrict__ gik, const float* __restrict__ entk,
                       const float* __restrict__ grv, const float* __restrict__ giv, const float* __restrict__ entv) {
    int p     = blockIdx.x;   // projection 0..2
    int which = blockIdx.y;   // 0: real, 1: imag
    const float* g = (p == 0) ? (which ? giq : grq)
                   : (p == 1) ? (which ? gik : grk)
                              : (which ? giv : grv);
    const float* e = (p == 0) ? entq : (p == 1) ? entk : entv;

    __shared__ float sg[64*64], se[64*64];
    for (int i = threadIdx.x; i < 4096; i += blockDim.x) { sg[i] = g[i]; se[i] = e[i]; }
    __syncthreads();
    for (int idx = threadIdx.x; idx < 4096; idx += blockDim.x) {
        int r = idx >> 6, c = idx & 63;
        float acc = 0.f;
#pragma unroll 8
        for (int k = 0; k < 64; k++) acc = fmaf(sg[r*64 + k], se[k*64 + c], acc);
        g_ge[p][which][idx] = acc;
    }
}

// ---------------------------------------------------------------------------
// Kernel 2: fused QNL per projection, per 64-token tile.
//  xe = X@enc -> er = xe@GRE, ei = xe@GIE -> prob = er^2+ei^2 -> prob@meas * sup_w
//  output to g_qkv[p] in (b,h,s,d) layout
// ---------------------------------------------------------------------------
__global__ void __launch_bounds__(256) k_qnl(const float* __restrict__ x,
                                             const float* __restrict__ enc0, const float* __restrict__ meas0,
                                             const float* __restrict__ enc1, const float* __restrict__ meas1,
                                             const float* __restrict__ enc2, const float* __restrict__ meas2,
                                             const float* __restrict__ supw) {
    const int p  = blockIdx.x / (NBS/64);
    const int rt = blockIdx.x % (NBS/64);
    const float* enc  = (p == 0) ? enc0  : (p == 1) ? enc1  : enc2;
    const float* meas = (p == 0) ? meas0 : (p == 1) ? meas1 : meas2;

    __shared__ float sA[64*65];
    __shared__ float sB[64*65];
    const int tid = threadIdx.x;
    const int ty = tid >> 4, tx = tid & 15;
    const int r0 = rt * 64;

    // -------- phase 1: XE = X_tile @ enc --------
    float acc[4][4];
#pragma unroll
    for (int i = 0; i < 4; i++)
#pragma unroll
        for (int j = 0; j < 4; j++) acc[i][j] = 0.f;

    for (int kt = 0; kt < 8; kt++) {
        load_tile_strided(sA, x + (size_t)r0 * ND + kt*64, ND, tid);
        load_tile_contig (sB, enc + (size_t)kt*64*NQ, tid);   // enc rows are 64 wide -> tile contiguous
        __syncthreads();
        mm64(acc, sA, sB, ty, tx);
        __syncthreads();
    }
    // store XE into sA
#pragma unroll
    for (int i = 0; i < 4; i++)
#pragma unroll
        for (int j = 0; j < 4; j++) sA[(ty*4+i)*65 + tx*4 + j] = acc[i][j];
    __syncthreads();

    // -------- phase 2: er/ei/prob --------
    for (int i = tid; i < 4096; i += 256) sB[(i>>6)*65 + (i&63)] = g_ge[p][0][i];
    __syncthreads();
    float er[4][4];
#pragma unroll
    for (int i = 0; i < 4; i++)
#pragma unroll
        for (int j = 0; j < 4; j++) er[i][j] = 0.f;
    mm64(er, sA, sB, ty, tx);
    __syncthreads();
    for (int i = tid; i < 4096; i += 256) sB[(i>>6)*65 + (i&63)] = g_ge[p][1][i];
    __syncthreads();
    float ei[4][4];
#pragma unroll
    for (int i = 0; i < 4; i++)
#pragma unroll
        for (int j = 0; j < 4; j++) ei[i][j] = 0.f;
    mm64(ei, sA, sB, ty, tx);
    // prob
#pragma unroll
    for (int i = 0; i < 4; i++)
#pragma unroll
        for (int j = 0; j < 4; j++) er[i][j] = er[i][j]*er[i][j] + ei[i][j]*ei[i][j];
    __syncthreads();           // everyone done reading XE (sA)
#pragma unroll
    for (int i = 0; i < 4; i++)
#pragma unroll
        for (int j = 0; j < 4; j++) sA[(ty*4+i)*65 + tx*4 + j] = er[i][j];
    __syncthreads();

    // -------- phase 3: out = prob @ meas, scale by sup_w, write (b,h,s,d) --------
    const int b  = r0 >> 11;       // /2048
    const int s0 = r0 & 2047;
    for (int ct = 0; ct < 8; ct++) {       // ct == head index
        load_tile_strided(sB, meas + (size_t)ct*64, ND, tid);
        __syncthreads();
        float o[4][4];
#pragma unroll
        for (int i = 0; i < 4; i++)
#pragma unroll
            for (int j = 0; j < 4; j++) o[i][j] = 0.f;
        mm64(o, sA, sB, ty, tx);
        float w[4];
#pragma unroll
        for (int j = 0; j < 4; j++) w[j] = supw[ct*NHD + tx*4 + j];
        float* outp = g_qkv[p] + ((size_t)(b*NH + ct)*NS + s0) * NHD;
#pragma unroll
        for (int i = 0; i < 4; i++)
#pragma unroll
            for (int j = 0; j < 4; j++)
                outp[(size_t)(ty*4 + i)*NHD + tx*4 + j] = o[i][j] * w[j];
        __syncthreads();
    }
}

// ---------------------------------------------------------------------------
// Kernel 3: qm = qs @ interf[h]  (per (b,h), 64-row tiles)
// ---------------------------------------------------------------------------
__global__ void __launch_bounds__(256) k_qm(const float* __restrict__ interf) {
    const int bh = blockIdx.x >> 5;       // /32
    const int st = blockIdx.x & 31;
    const int h  = bh % NH;
    __shared__ float sA[64*65];
    __shared__ float sB[64*65];
    const int tid = threadIdx.x;
    const int ty = tid >> 4, tx = tid & 15;

    const float* Ap = g_qkv[0] + ((size_t)bh*NS + st*64) * NHD;   // contiguous 64x64
    load_tile_contig(sA, Ap, tid);
    load_tile_contig(sB, interf + (size_t)h*NHD*NHD, tid);
    __syncthreads();

    float o[4][4];
#pragma unroll
    for (int i = 0; i < 4; i++)
#pragma unroll
        for (int j = 0; j < 4; j++) o[i][j] = 0.f;
    mm64(o, sA, sB, ty, tx);

    float* Op = g_qm + ((size_t)bh*NS + st*64) * NHD;
#pragma unroll
    for (int i = 0; i < 4; i++)
#pragma unroll
        for (int j = 0; j < 4; j++)
            Op[(size_t)(ty*4 + i)*NHD + tx*4 + j] = o[i][j];
}

// ---------------------------------------------------------------------------
// Kernel 4: flash attention, fp32, 64x64 tiles, online softmax.
//  smem: sQ | sK (reused as P) | sV  => 3 * 64*65 floats (dynamic, 49920 B)
// ---------------------------------------------------------------------------
extern __shared__ float at_smem[];
__global__ void __launch_bounds__(256) k_attn() {
    const int bh = blockIdx.x >> 5;
    const int qt = blockIdx.x & 31;
    float* sQ = at_smem;
    float* sK = at_smem + 64*65;     // also holds P after scores consumed
    float* sV = at_smem + 2*64*65;
    const int tid = threadIdx.x;
    const int ty = tid >> 4, tx = tid & 15;

    load_tile_contig(sQ, g_qm + ((size_t)bh*NS + qt*64) * NHD, tid);

    float m_old[4], l[4], o[4][4];
#pragma unroll
    for (int i = 0; i < 4; i++) { m_old[i] = -1e30f; l[i] = 0.f; }
#pragma unroll
    for (int i = 0; i < 4; i++)
#pragma unroll
        for (int j = 0; j < 4; j++) o[i][j] = 0.f;

    for (int jt = 0; jt < NS/64; jt++) {
        load_tile_contig(sK, g_qkv[1] + ((size_t)bh*NS + jt*64) * NHD, tid);
        load_tile_contig(sV, g_qkv[2] + ((size_t)bh*NS + jt*64) * NHD, tid);
        __syncthreads();

        float s[4][4];
#pragma unroll
        for (int i = 0; i < 4; i++)
#pragma unroll
            for (int j = 0; j < 4; j++) s[i][j] = 0.f;
        mm64_bt(s, sQ, sK, ty, tx);          // S = Q @ K^T
#pragma unroll
        for (int i = 0; i < 4; i++)
#pragma unroll
            for (int j = 0; j < 4; j++) s[i][j] *= 0.125f;   // 1/sqrt(64)

        // row-wise online softmax (rows shared by 16 lanes with same ty)
        float tm[4];
#pragma unroll
        for (int i = 0; i < 4; i++) {
            tm[i] = fmaxf(fmaxf(s[i][0], s[i][1]), fmaxf(s[i][2], s[i][3]));
#pragma unroll
            for (int off = 8; off >= 1; off >>= 1)
                tm[i] = fmaxf(tm[i], __shfl_xor_sync(0xffffffffu, tm[i], off, 16));
        }
        float c[4], rs[4];
#pragma unroll
        for (int i = 0; i < 4; i++) {
            float mn = fmaxf(m_old[i], tm[i]);
            c[i] = __expf(m_old[i] - mn);
            m_old[i] = mn;
#pragma unroll
            for (int j = 0; j < 4; j++) s[i][j] = __expf(s[i][j] - mn);
            rs[i] = s[i][0] + s[i][1] + s[i][2] + s[i][3];
#pragma unroll
            for (int off = 8; off >= 1; off >>= 1)
                rs[i] += __shfl_xor_sync(0xffffffffu, rs[i], off, 16);
            l[i] = l[i]*c[i] + rs[i];
#pragma unroll
            for (int j = 0; j < 4; j++) o[i][j] *= c[i];
        }

        __syncthreads();          // everyone done reading sK (scores)
#pragma unroll
        for (int i = 0; i < 4; i++)
#pragma unroll
            for (int j = 0; j < 4; j++) sK[(ty*4+i)*65 + tx*4 + j] = s[i][j];
        __syncthreads();

        mm64(o, sK, sV, ty, tx);             // O += P @ V
        __syncthreads();                     // before next tile overwrites sK/sV
    }

    const int b = bh / NH, h = bh % NH;
#pragma unroll
    for (int i = 0; i < 4; i++) {
        float inv = 1.f / l[i];
        int srow = qt*64 + ty*4 + i;
#pragma unroll
        for (int j = 0; j < 4; j++)
            g_ao[((size_t)b*NS + srow)*ND + h*NHD + tx*4 + j] = o[i][j] * inv;
    }
}

// ---------------------------------------------------------------------------
// Kernel 5: final projection: out = g_ao @ w_out + b_out
// ---------------------------------------------------------------------------
__global__ void __launch_bounds__(256) k_proj(const float* __restrict__ w,
                                              const float* __restrict__ bias,
                                              float* __restrict__ out) {
    const int rt = blockIdx.x;   // 0..63 row tiles
    const int ct = blockIdx.y;   // 0..7 col tiles
    __shared__ float sA[64*65];
    __shared__ float sB[64*65];
    const int tid = threadIdx.x;
    const int ty = tid >> 4, tx = tid & 15;
    const int r0 = rt * 64;

    float acc[4][4];
#pragma unroll
    for (int i = 0; i < 4; i++)
#pragma unroll
        for (int j = 0; j < 4; j++) acc[i][j] = 0.f;

    for (int kt = 0; kt < 8; kt++) {
        load_tile_strided(sA, g_ao + (size_t)r0*ND + kt*64, ND, tid);
        load_tile_strided(sB, w + (size_t)kt*64*ND + ct*64, ND, tid);
        __syncthreads();
        mm64(acc, sA, sB, ty, tx);
        __syncthreads();
    }
    float bb[4];
#pragma unroll
    for (int j = 0; j < 4; j++) bb[j] = bias[ct*64 + tx*4 + j];
#pragma unroll
    for (int i = 0; i < 4; i++)
#pragma unroll
        for (int j = 0; j < 4; j++)
            out[(size_t)(r0 + ty*4 + i)*ND + ct*64 + tx*4 + j] = acc[i][j] + bb[j];
}

// ---------------------------------------------------------------------------
extern "C" void kernel_launch(void* const* d_in, const int* in_sizes, int n_in,
                              void* d_out, int out_size) {
    const float* x      = (const float*)d_in[0];
    const float* q_enc  = (const float*)d_in[1];
    const float* q_gr   = (const float*)d_in[2];
    const float* q_gi   = (const float*)d_in[3];
    const float* q_ent  = (const float*)d_in[4];
    const float* q_meas = (const float*)d_in[5];
    const float* k_enc  = (const float*)d_in[6];
    const float* k_gr   = (const float*)d_in[7];
    const float* k_gi   = (const float*)d_in[8];
    const float* k_ent  = (const float*)d_in[9];
    const float* k_meas = (const float*)d_in[10];
    const float* v_enc  = (const float*)d_in[11];
    const float* v_gr   = (const float*)d_in[12];
    const float* v_gi   = (const float*)d_in[13];
    const float* v_ent  = (const float*)d_in[14];
    const float* v_meas = (const float*)d_in[15];
    const float* sup_w  = (const float*)d_in[16];
    const float* interf = (const float*)d_in[17];
    const float* w_out  = (const float*)d_in[18];
    const float* b_out  = (const float*)d_in[19];
    float* out = (float*)d_out;

    static const int ATT_SMEM = 3 * 64 * 65 * (int)sizeof(float);   // 49920
    cudaFuncSetAttribute(k_attn, cudaFuncAttributeMaxDynamicSharedMemorySize, ATT_SMEM);

    k_prep<<<dim3(3, 2), 256>>>(q_gr, q_gi, q_ent, k_gr, k_gi, k_ent, v_gr, v_gi, v_ent);
    k_qnl<<<3 * (NBS/64), 256>>>(x, q_enc, q_meas, k_enc, k_meas, v_enc, v_meas, sup_w);
    k_qm<<<NB*NH*(NS/64), 256>>>(interf);
    k_attn<<<NB*NH*(NS/64), 256, ATT_SMEM>>>();
    k_proj<<<dim3(NBS/64, ND/64), 256>>>(w_out, b_out, out);
}

// round 3
// speedup vs baseline: 1.8760x; 1.8760x over previous
#include <cuda_runtime.h>
#include <cstdint>

// Problem constants
#define NB   2
#define NS   2048
#define ND   512
#define NH   8
#define NQ   64
#define NHD  64
#define NBS  (NB*NS)             // 4096 tokens
#define QKV_ELEMS (NB*NH*NS*NHD) // 2,097,152

// Scratch (device globals; no allocations allowed)
__device__ float g_ge[3][2][NQ*NQ];      // folded gr@ent / gi@ent per projection
__device__ float g_m2[NH][NQ*NHD];       // (q_meas[:,h] . w_h) @ interf[h] * 0.125
__device__ float g_qkv[3][QKV_ELEMS];    // qm / ks / vs in (b,h,s,d), tf32-rounded
__device__ float g_ao[NBS*ND];           // attention out, (b,s,D)

// ---------------------------------------------------------------------------
// helpers
// ---------------------------------------------------------------------------
__device__ __forceinline__ uint32_t fbits(float x) { return __float_as_uint(x); }

__device__ __forceinline__ float to_tf32(float x) {
    float r;
    asm("cvt.rna.tf32.f32 %0, %1;" : "=f"(r) : "f"(x));
    return r;
}

__device__ __forceinline__ void mma_tf32(float d[4], const uint32_t a[4],
                                         const uint32_t b[2], const float c[4]) {
    asm volatile("mma.sync.aligned.m16n8k8.row.col.f32.tf32.tf32.f32 "
                 "{%0,%1,%2,%3}, {%4,%5,%6,%7}, {%8,%9}, {%10,%11,%12,%13};"
                 : "=f"(d[0]), "=f"(d[1]), "=f"(d[2]), "=f"(d[3])
                 : "r"(a[0]), "r"(a[1]), "r"(a[2]), "r"(a[3]),
                   "r"(b[0]), "r"(b[1]),
                   "f"(c[0]), "f"(c[1]), "f"(c[2]), "f"(c[3]));
}

// 64x64 tile load into smem (stride 65) from global with row stride ldg
__device__ __forceinline__ void load_tile_strided(float* s, const float* g, int ldg, int tid) {
#pragma unroll
    for (int i = 0; i < 4; i++) {
        int idx = tid + 256 * i;
        int row = idx >> 4;
        int c   = (idx & 15) * 4;
        float4 v = *reinterpret_cast<const float4*>(g + (size_t)row * ldg + c);
        s[row*65 + c + 0] = v.x;
        s[row*65 + c + 1] = v.y;
        s[row*65 + c + 2] = v.z;
        s[row*65 + c + 3] = v.w;
    }
}

__device__ __forceinline__ void load_tile_contig(float* s, const float* g, int tid) {
#pragma unroll
    for (int i = 0; i < 4; i++) {
        int idx = tid + 256 * i;
        float4 v = reinterpret_cast<const float4*>(g)[idx];
        int row = idx >> 4;
        int c   = (idx & 15) * 4;
        s[row*65 + c + 0] = v.x;
        s[row*65 + c + 1] = v.y;
        s[row*65 + c + 2] = v.z;
        s[row*65 + c + 3] = v.w;
    }
}

// 64x64 tile load into smem with smem row stride lds, global contiguous 64x64
__device__ __forceinline__ void load_tile_s(float* s, int lds, const float* g, int tid) {
#pragma unroll
    for (int i = 0; i < 4; i++) {
        int idx = tid + 256 * i;
        float4 v = reinterpret_cast<const float4*>(g)[idx];
        int row = idx >> 4;
        int c   = (idx & 15) * 4;
        s[row*lds + c + 0] = v.x;
        s[row*lds + c + 1] = v.y;
        s[row*lds + c + 2] = v.z;
        s[row*lds + c + 3] = v.w;
    }
}

// C[64x64] += A * B (row-major, stride 65), 4x4 per thread, 16x16 thread grid
__device__ __forceinline__ void mm64(float acc[4][4], const float* A, const float* Bm, int ty, int tx) {
#pragma unroll 8
    for (int kk = 0; kk < 64; kk++) {
        float a[4], b[4];
#pragma unroll
        for (int i = 0; i < 4; i++) a[i] = A[(ty*4 + i)*65 + kk];
#pragma unroll
        for (int j = 0; j < 4; j++) b[j] = Bm[kk*65 + tx*4 + j];
#pragma unroll
        for (int i = 0; i < 4; i++)
#pragma unroll
            for (int j = 0; j < 4; j++)
                acc[i][j] = fmaf(a[i], b[j], acc[i][j]);
    }
}

// ---------------------------------------------------------------------------
// Kernel 1: fold gate matrices (gr@ent, gi@ent) and M2 = (q_meas.h w_h)@interf_h/8
// ---------------------------------------------------------------------------
__global__ void k_prep(const float* __restrict__ grq, const float* __restrict__ giq, const float* __restrict__ entq,
                       const float* __restrict__ grk, const float* __restrict__ gik, const float* __restrict__ entk,
                       const float* __restrict__ grv, const float* __restrict__ giv, const float* __restrict__ entv,
                       const float* __restrict__ qmeas, const float* __restrict__ supw,
                       const float* __restrict__ interf) {
    __shared__ float sg[64*64], se[64*64];
    const int bx = blockIdx.x;
    const int tid = threadIdx.x;

    if (bx < 6) {
        int p = bx >> 1, which = bx & 1;
        const float* g = (p == 0) ? (which ? giq : grq)
                       : (p == 1) ? (which ? gik : grk)
                                  : (which ? giv : grv);
        const float* e = (p == 0) ? entq : (p == 1) ? entk : entv;
        for (int i = tid; i < 4096; i += blockDim.x) { sg[i] = g[i]; se[i] = e[i]; }
        __syncthreads();
        for (int idx = tid; idx < 4096; idx += blockDim.x) {
            int r = idx >> 6, c = idx & 63;
            float acc = 0.f;
#pragma unroll 8
            for (int k = 0; k < 64; k++) acc = fmaf(sg[r*64 + k], se[k*64 + c], acc);
            g_ge[p][which][idx] = acc;
        }
    } else {
        int h = bx - 6;
        for (int i = tid; i < 4096; i += blockDim.x) {
            int r = i >> 6, c = i & 63;
            sg[i] = qmeas[(size_t)r * ND + h*64 + c] * supw[h*64 + c];
            se[i] = interf[(size_t)h*4096 + i];
        }
        __syncthreads();
        for (int idx = tid; idx < 4096; idx += blockDim.x) {
            int r = idx >> 6, c = idx & 63;
            float acc = 0.f;
#pragma unroll 8
            for (int k = 0; k < 64; k++) acc = fmaf(sg[r*64 + k], se[k*64 + c], acc);
            g_m2[h][idx] = acc * 0.125f;   // fold 1/sqrt(HD)
        }
    }
}

// ---------------------------------------------------------------------------
// Kernel 2: fused QNL per projection, per 64-token tile.
//  p==0 uses M2 (meas . w @ interf / 8) -> output IS qm. p==1/2 apply sup_w at store.
//  All stores tf32-rounded (consumed by tf32 MMAs in k_attn).
// ---------------------------------------------------------------------------
__global__ void __launch_bounds__(256) k_qnl(const float* __restrict__ x,
                                             const float* __restrict__ enc0, const float* __restrict__ meas0,
                                             const float* __restrict__ enc1, const float* __restrict__ meas1,
                                             const float* __restrict__ enc2, const float* __restrict__ meas2,
                                             const float* __restrict__ supw) {
    const int p  = blockIdx.x / (NBS/64);
    const int rt = blockIdx.x % (NBS/64);
    const float* enc  = (p == 0) ? enc0  : (p == 1) ? enc1  : enc2;
    const float* meas = (p == 0) ? meas0 : (p == 1) ? meas1 : meas2;

    __shared__ float sA[64*65];
    __shared__ float sB[64*65];
    const int tid = threadIdx.x;
    const int ty = tid >> 4, tx = tid & 15;
    const int r0 = rt * 64;

    // phase 1: XE = X_tile @ enc
    float acc[4][4];
#pragma unroll
    for (int i = 0; i < 4; i++)
#pragma unroll
        for (int j = 0; j < 4; j++) acc[i][j] = 0.f;

    for (int kt = 0; kt < 8; kt++) {
        load_tile_strided(sA, x + (size_t)r0 * ND + kt*64, ND, tid);
        load_tile_contig (sB, enc + (size_t)kt*64*NQ, tid);
        __syncthreads();
        mm64(acc, sA, sB, ty, tx);
        __syncthreads();
    }
#pragma unroll
    for (int i = 0; i < 4; i++)
#pragma unroll
        for (int j = 0; j < 4; j++) sA[(ty*4+i)*65 + tx*4 + j] = acc[i][j];
    __syncthreads();

    // phase 2: er/ei -> prob
    for (int i = tid; i < 4096; i += 256) sB[(i>>6)*65 + (i&63)] = g_ge[p][0][i];
    __syncthreads();
    float er[4][4];
#pragma unroll
    for (int i = 0; i < 4; i++)
#pragma unroll
        for (int j = 0; j < 4; j++) er[i][j] = 0.f;
    mm64(er, sA, sB, ty, tx);
    __syncthreads();
    for (int i = tid; i < 4096; i += 256) sB[(i>>6)*65 + (i&63)] = g_ge[p][1][i];
    __syncthreads();
    float ei[4][4];
#pragma unroll
    for (int i = 0; i < 4; i++)
#pragma unroll
        for (int j = 0; j < 4; j++) ei[i][j] = 0.f;
    mm64(ei, sA, sB, ty, tx);
#pragma unroll
    for (int i = 0; i < 4; i++)
#pragma unroll
        for (int j = 0; j < 4; j++) er[i][j] = er[i][j]*er[i][j] + ei[i][j]*ei[i][j];
    __syncthreads();
#pragma unroll
    for (int i = 0; i < 4; i++)
#pragma unroll
        for (int j = 0; j < 4; j++) sA[(ty*4+i)*65 + tx*4 + j] = er[i][j];
    __syncthreads();

    // phase 3: out = prob @ (M2 or meas), write (b,h,s,d), tf32-rounded
    const int b  = r0 >> 11;
    const int s0 = r0 & 2047;
    for (int ct = 0; ct < 8; ct++) {       // ct == head index
        if (p == 0) load_tile_contig(sB, g_m2[ct], tid);
        else        load_tile_strided(sB, meas + (size_t)ct*64, ND, tid);
        __syncthreads();
        float o[4][4];
#pragma unroll
        for (int i = 0; i < 4; i++)
#pragma unroll
            for (int j = 0; j < 4; j++) o[i][j] = 0.f;
        mm64(o, sA, sB, ty, tx);
        float w[4];
        if (p != 0) {
#pragma unroll
            for (int j = 0; j < 4; j++) w[j] = supw[ct*NHD + tx*4 + j];
        } else {
#pragma unroll
            for (int j = 0; j < 4; j++) w[j] = 1.f;
        }
        float* outp = g_qkv[p] + ((size_t)(b*NH + ct)*NS + s0) * NHD;
#pragma unroll
        for (int i = 0; i < 4; i++)
#pragma unroll
            for (int j = 0; j < 4; j++)
                outp[(size_t)(ty*4 + i)*NHD + tx*4 + j] = to_tf32(o[i][j] * w[j]);
        __syncthreads();
    }
}

// ---------------------------------------------------------------------------
// Kernel 3: flash attention via mma.sync m16n8k8 tf32, 64x64 tiles.
// ---------------------------------------------------------------------------
#define LDQ 68
#define LDV 72
#define ATT_SMEM_FLOATS (3*64*LDQ + 64*LDV + 128)

#define EXP16_ONE(vv) do {                         \
    float t = to_tf32(__expf((vv) - mnew));        \
    (vv) = t; sum += t; } while (0)

__global__ void __launch_bounds__(256) k_attn() {
    extern __shared__ float sm[];
    float* sQ = sm;
    float* sK = sQ + 64*LDQ;
    float* sS = sK + 64*LDQ;
    float* sV = sS + 64*LDQ;
    float* sc = sV + 64*LDV;   // 64 correction factors
    float* sl = sc + 64;       // 64 row sums (epilogue)

    const int tid  = threadIdx.x;
    const int lane = tid & 31;
    const int warp = tid >> 5;
    const int bh = blockIdx.x >> 5;
    const int qt = blockIdx.x & 31;
    const int wr = (warp >> 1) << 4;
    const int wc = (warp & 1) << 5;
    const int g4 = lane >> 2;
    const int l4 = lane & 3;
    const int srow = tid >> 2;        // softmax row owned by this thread
    const int sseg = (tid & 3) << 4;  // 16-col segment

    load_tile_s(sQ, LDQ, g_qkv[0] + ((size_t)bh*NS + qt*64)*NHD, tid);

    float o[4][4];
#pragma unroll
    for (int ds = 0; ds < 4; ds++)
#pragma unroll
        for (int j = 0; j < 4; j++) o[ds][j] = 0.f;
    float mrow = -1e30f, lrow = 0.f;

    for (int jt = 0; jt < NS/64; jt++) {
        load_tile_s(sK, LDQ, g_qkv[1] + ((size_t)bh*NS + jt*64)*NHD, tid);
        load_tile_s(sV, LDV, g_qkv[2] + ((size_t)bh*NS + jt*64)*NHD, tid);
        __syncthreads();

        // ---- S = Q @ K^T (scale folded into Q) ----
        float sf[4][4];
#pragma unroll
        for (int ns = 0; ns < 4; ns++)
#pragma unroll
            for (int j = 0; j < 4; j++) sf[ns][j] = 0.f;
#pragma unroll
        for (int kk = 0; kk < 8; kk++) {
            uint32_t a[4];
            const float* qp = sQ + (wr + g4)*LDQ + kk*8 + l4;
            a[0] = fbits(qp[0]);       a[1] = fbits(qp[8*LDQ]);
            a[2] = fbits(qp[4]);       a[3] = fbits(qp[8*LDQ + 4]);
#pragma unroll
            for (int ns = 0; ns < 4; ns++) {
                const float* kp = sK + (wc + ns*8 + g4)*LDQ + kk*8 + l4;
                uint32_t b[2] = { fbits(kp[0]), fbits(kp[4]) };
                mma_tf32(sf[ns], a, b, sf[ns]);
            }
        }
#pragma unroll
        for (int ns = 0; ns < 4; ns++) {
            float* sp = sS + (wr + g4)*LDQ + wc + ns*8 + 2*l4;
            sp[0] = sf[ns][0]; sp[1] = sf[ns][1];
            sp[8*LDQ] = sf[ns][2]; sp[8*LDQ + 1] = sf[ns][3];
        }
        __syncthreads();

        // ---- online softmax: thread owns 16 cols of one row (component-wise,
        //      NO pointer-walk over distinct locals) ----
        {
            float* rp = sS + srow*LDQ + sseg;
            float4 v0 = *reinterpret_cast<float4*>(rp + 0);
            float4 v1 = *reinterpret_cast<float4*>(rp + 4);
            float4 v2 = *reinterpret_cast<float4*>(rp + 8);
            float4 v3 = *reinterpret_cast<float4*>(rp + 12);
            float mx = fmaxf(fmaxf(fmaxf(v0.x, v0.y), fmaxf(v0.z, v0.w)),
                             fmaxf(fmaxf(v1.x, v1.y), fmaxf(v1.z, v1.w)));
            mx = fmaxf(mx, fmaxf(fmaxf(fmaxf(v2.x, v2.y), fmaxf(v2.z, v2.w)),
                                 fmaxf(fmaxf(v3.x, v3.y), fmaxf(v3.z, v3.w))));
            mx = fmaxf(mx, __shfl_xor_sync(0xffffffffu, mx, 1));
            mx = fmaxf(mx, __shfl_xor_sync(0xffffffffu, mx, 2));
            float mnew = fmaxf(mrow, mx);
            float corr = __expf(mrow - mnew);
            float sum = 0.f;
            EXP16_ONE(v0.x); EXP16_ONE(v0.y); EXP16_ONE(v0.z); EXP16_ONE(v0.w);
            EXP16_ONE(v1.x); EXP16_ONE(v1.y); EXP16_ONE(v1.z); EXP16_ONE(v1.w);
            EXP16_ONE(v2.x); EXP16_ONE(v2.y); EXP16_ONE(v2.z); EXP16_ONE(v2.w);
            EXP16_ONE(v3.x); EXP16_ONE(v3.y); EXP16_ONE(v3.z); EXP16_ONE(v3.w);
            sum += __shfl_xor_sync(0xffffffffu, sum, 1);
            sum += __shfl_xor_sync(0xffffffffu, sum, 2);
            lrow = lrow * corr + sum;
            mrow = mnew;
            *reinterpret_cast<float4*>(rp + 0)  = v0;
            *reinterpret_cast<float4*>(rp + 4)  = v1;
            *reinterpret_cast<float4*>(rp + 8)  = v2;
            *reinterpret_cast<float4*>(rp + 12) = v3;
            if ((tid & 3) == 0) sc[srow] = corr;
        }
        __syncthreads();

        // ---- rescale O, then O += P @ V ----
        float cf0 = sc[wr + g4], cf1 = sc[wr + g4 + 8];
#pragma unroll
        for (int ds = 0; ds < 4; ds++) {
            o[ds][0] *= cf0; o[ds][1] *= cf0;
            o[ds][2] *= cf1; o[ds][3] *= cf1;
        }
#pragma unroll
        for (int kk = 0; kk < 8; kk++) {
            uint32_t a[4];
            const float* pp = sS + (wr + g4)*LDQ + kk*8 + l4;
            a[0] = fbits(pp[0]);       a[1] = fbits(pp[8*LDQ]);
            a[2] = fbits(pp[4]);       a[3] = fbits(pp[8*LDQ + 4]);
#pragma unroll
            for (int ds = 0; ds < 4; ds++) {
                const float* vp = sV + (kk*8 + l4)*LDV + wc + ds*8 + g4;
                uint32_t b[2] = { fbits(vp[0]), fbits(vp[4*LDV]) };
                mma_tf32(o[ds], a, b, o[ds]);
            }
        }
        __syncthreads();
    }

    if ((tid & 3) == 0) sl[srow] = lrow;
    __syncthreads();

    const float inv0 = 1.f / sl[wr + g4];
    const float inv1 = 1.f / sl[wr + g4 + 8];
    const int b = bh >> 3, h = bh & 7;
    const int r0 = qt*64 + wr + g4;
    float* base = g_ao + ((size_t)b*NS + r0)*ND + h*64 + wc;
#pragma unroll
    for (int ds = 0; ds < 4; ds++) {
        int c = ds*8 + 2*l4;
        base[c]            = o[ds][0] * inv0;
        base[c + 1]        = o[ds][1] * inv0;
        base[8*ND + c]     = o[ds][2] * inv1;
        base[8*ND + c + 1] = o[ds][3] * inv1;
    }
}

// ---------------------------------------------------------------------------
// Kernel 4: final projection: out = g_ao @ w_out + b_out
// ---------------------------------------------------------------------------
__global__ void __launch_bounds__(256) k_proj(const float* __restrict__ w,
                                              const float* __restrict__ bias,
                                              float* __restrict__ out) {
    const int rt = blockIdx.x;
    const int ct = blockIdx.y;
    __shared__ float sA[64*65];
    __shared__ float sB[64*65];
    const int tid = threadIdx.x;
    const int ty = tid >> 4, tx = tid & 15;
    const int r0 = rt * 64;

    float acc[4][4];
#pragma unroll
    for (int i = 0; i < 4; i++)
#pragma unroll
        for (int j = 0; j < 4; j++) acc[i][j] = 0.f;

    for (int kt = 0; kt < 8; kt++) {
        load_tile_strided(sA, g_ao + (size_t)r0*ND + kt*64, ND, tid);
        load_tile_strided(sB, w + (size_t)kt*64*ND + ct*64, ND, tid);
        __syncthreads();
        mm64(acc, sA, sB, ty, tx);
        __syncthreads();
    }
    float bb[4];
#pragma unroll
    for (int j = 0; j < 4; j++) bb[j] = bias[ct*64 + tx*4 + j];
#pragma unroll
    for (int i = 0; i < 4; i++)
#pragma unroll
        for (int j = 0; j < 4; j++)
            out[(size_t)(r0 + ty*4 + i)*ND + ct*64 + tx*4 + j] = acc[i][j] + bb[j];
}

// ---------------------------------------------------------------------------
extern "C" void kernel_launch(void* const* d_in, const int* in_sizes, int n_in,
                              void* d_out, int out_size) {
    const float* x      = (const float*)d_in[0];
    const float* q_enc  = (const float*)d_in[1];
    const float* q_gr   = (const float*)d_in[2];
    const float* q_gi   = (const float*)d_in[3];
    const float* q_ent  = (const float*)d_in[4];
    const float* q_meas = (const float*)d_in[5];
    const float* k_enc  = (const float*)d_in[6];
    const float* k_gr   = (const float*)d_in[7];
    const float* k_gi   = (const float*)d_in[8];
    const float* k_ent  = (const float*)d_in[9];
    const float* k_meas = (const float*)d_in[10];
    const float* v_enc  = (const float*)d_in[11];
    const float* v_gr   = (const float*)d_in[12];
    const float* v_gi   = (const float*)d_in[13];
    const float* v_ent  = (const float*)d_in[14];
    const float* v_meas = (const float*)d_in[15];
    const float* sup_w  = (const float*)d_in[16];
    const float* interf = (const float*)d_in[17];
    const float* w_out  = (const float*)d_in[18];
    const float* b_out  = (const float*)d_in[19];
    float* out = (float*)d_out;

    static const int ATT_SMEM = ATT_SMEM_FLOATS * (int)sizeof(float);  // 71168 B
    cudaFuncSetAttribute(k_attn, cudaFuncAttributeMaxDynamicSharedMemorySize, ATT_SMEM);

    k_prep<<<14, 256>>>(q_gr, q_gi, q_ent, k_gr, k_gi, k_ent, v_gr, v_gi, v_ent,
                        q_meas, sup_w, interf);
    k_qnl<<<3 * (NBS/64), 256>>>(x, q_enc, q_meas, k_enc, k_meas, v_enc, v_meas, sup_w);
    k_attn<<<NB*NH*(NS/64), 256, ATT_SMEM>>>();
    k_proj<<<dim3(NBS/64, ND/64), 256>>>(w_out, b_out, out);
}

// round 4
// speedup vs baseline: 2.5659x; 1.3677x over previous
#include <cuda_runtime.h>
#include <cstdint>

// Problem constants
#define NB   2
#define NS   2048
#define ND   512
#define NH   8
#define NQ   64
#define NHD  64
#define NBS  (NB*NS)             // 4096 tokens
#define QKV_ELEMS (NB*NH*NS*NHD) // 2,097,152

// Scratch (device globals; no allocations allowed)
__device__ float g_geT[3][2][NQ*NQ];     // (gr@ent)^T per projection, tf32
__device__ float g_m2T[NH][NQ*NHD];      // ((q_meas.h w_h)@interf_h/8)^T, tf32
__device__ float g_encT[3][NQ*ND];       // enc^T [64][512], tf32
__device__ float g_measT[3][ND*NQ];      // meas^T [512][64], w folded (p=1,2), tf32
__device__ float g_woT[ND*ND];           // w_out^T [512][512], tf32
__device__ float g_qkv[3][QKV_ELEMS];    // qm / ks / vs in (b,h,s,d), tf32-rounded
__device__ float g_ao[NBS*ND];           // attention out, (b,s,D)

// ---------------------------------------------------------------------------
// helpers
// ---------------------------------------------------------------------------
__device__ __forceinline__ uint32_t fbits(float x) { return __float_as_uint(x); }

__device__ __forceinline__ float to_tf32(float x) {
    float r;
    asm("cvt.rna.tf32.f32 %0, %1;" : "=f"(r) : "f"(x));
    return r;
}

__device__ __forceinline__ void mma_tf32(float d[4], const uint32_t a[4],
                                         const uint32_t b[2], const float c[4]) {
    asm volatile("mma.sync.aligned.m16n8k8.row.col.f32.tf32.tf32.f32 "
                 "{%0,%1,%2,%3}, {%4,%5,%6,%7}, {%8,%9}, {%10,%11,%12,%13};"
                 : "=f"(d[0]), "=f"(d[1]), "=f"(d[2]), "=f"(d[3])
                 : "r"(a[0]), "r"(a[1]), "r"(a[2]), "r"(a[3]),
                   "r"(b[0]), "r"(b[1]),
                   "f"(c[0]), "f"(c[1]), "f"(c[2]), "f"(c[3]));
}

#define LDA 68   // smem stride for MMA GEMM tiles (conflict-free fragment loads)
#define LDQ 68
#define LDV 72

// 64x64 tile load: global (row stride ldg) -> smem (row stride LDA)
__device__ __forceinline__ void ld_tile(float* s, const float* g, int ldg, int tid) {
#pragma unroll
    for (int i = 0; i < 4; i++) {
        int idx = tid + 256 * i;
        int row = idx >> 4;
        int c   = (idx & 15) * 4;
        float4 v = *reinterpret_cast<const float4*>(g + (size_t)row * ldg + c);
        s[row*LDA + c + 0] = v.x;
        s[row*LDA + c + 1] = v.y;
        s[row*LDA + c + 2] = v.z;
        s[row*LDA + c + 3] = v.w;
    }
}

// same, with tf32 rounding of each element
__device__ __forceinline__ void ld_tile_cvt(float* s, const float* g, int ldg, int tid) {
#pragma unroll
    for (int i = 0; i < 4; i++) {
        int idx = tid + 256 * i;
        int row = idx >> 4;
        int c   = (idx & 15) * 4;
        float4 v = *reinterpret_cast<const float4*>(g + (size_t)row * ldg + c);
        s[row*LDA + c + 0] = to_tf32(v.x);
        s[row*LDA + c + 1] = to_tf32(v.y);
        s[row*LDA + c + 2] = to_tf32(v.z);
        s[row*LDA + c + 3] = to_tf32(v.w);
    }
}

// 64x64 tile load with explicit smem stride (attention buffers)
__device__ __forceinline__ void load_tile_s(float* s, int lds, const float* g, int tid) {
#pragma unroll
    for (int i = 0; i < 4; i++) {
        int idx = tid + 256 * i;
        float4 v = reinterpret_cast<const float4*>(g)[idx];
        int row = idx >> 4;
        int c   = (idx & 15) * 4;
        s[row*lds + c + 0] = v.x;
        s[row*lds + c + 1] = v.y;
        s[row*lds + c + 2] = v.z;
        s[row*lds + c + 3] = v.w;
    }
}

// 64x64 MMA GEMM: C(16x32 per warp) += A[m][k] * B[n][k], both stride LDA
__device__ __forceinline__ void gemm64_acc(float (&sf)[4][4], const float* sA, const float* sB,
                                           int wr, int wc, int g4, int l4) {
#pragma unroll
    for (int kk = 0; kk < 8; kk++) {
        uint32_t a[4];
        const float* ap = sA + (wr + g4)*LDA + kk*8 + l4;
        a[0] = fbits(ap[0]);       a[1] = fbits(ap[8*LDA]);
        a[2] = fbits(ap[4]);       a[3] = fbits(ap[8*LDA + 4]);
#pragma unroll
        for (int ns = 0; ns < 4; ns++) {
            const float* bp = sB + (wc + ns*8 + g4)*LDA + kk*8 + l4;
            uint32_t b[2] = { fbits(bp[0]), fbits(bp[4]) };
            mma_tf32(sf[ns], a, b, sf[ns]);
        }
    }
}

// write C fragments into stride-LDA smem, tf32-rounded
__device__ __forceinline__ void frag_to_smem(float* s, const float (&f)[4][4],
                                             int wr, int wc, int g4, int l4) {
#pragma unroll
    for (int ns = 0; ns < 4; ns++) {
        float* sp = s + (wr + g4)*LDA + wc + ns*8 + 2*l4;
        sp[0] = to_tf32(f[ns][0]); sp[1] = to_tf32(f[ns][1]);
        sp[8*LDA] = to_tf32(f[ns][2]); sp[8*LDA + 1] = to_tf32(f[ns][3]);
    }
}

// ---------------------------------------------------------------------------
// Kernel 1: prep — folded gates (transposed), M2^T, enc^T, meas^T(.w), w_out^T
// ---------------------------------------------------------------------------
__device__ __forceinline__ void transpose_tile(float* dst, int ldd, const float* src, int ldsrc,
                                               const float* rowscale, int tid, float* sg) {
    for (int idx = tid; idx < 4096; idx += 256) {
        int r = idx >> 6, c = idx & 63;
        sg[r*65 + c] = src[(size_t)r*ldsrc + c];
    }
    __syncthreads();
    for (int idx = tid; idx < 4096; idx += 256) {
        int n = idx >> 6, k = idx & 63;
        float v = sg[k*65 + n];
        if (rowscale) v *= rowscale[n];
        dst[(size_t)n*ldd + k] = to_tf32(v);
    }
    __syncthreads();
}

__global__ void k_prep(const float* __restrict__ grq, const float* __restrict__ giq, const float* __restrict__ entq,
                       const float* __restrict__ grk, const float* __restrict__ gik, const float* __restrict__ entk,
                       const float* __restrict__ grv, const float* __restrict__ giv, const float* __restrict__ entv,
                       const float* __restrict__ qmeas, const float* __restrict__ kmeas, const float* __restrict__ vmeas,
                       const float* __restrict__ qenc, const float* __restrict__ kenc, const float* __restrict__ venc,
                       const float* __restrict__ supw, const float* __restrict__ interf,
                       const float* __restrict__ wout) {
    __shared__ float sg[64*65];
    __shared__ float se[64*64];
    const int bx = blockIdx.x;
    const int tid = threadIdx.x;

    if (bx < 6) {
        // g_geT[p][which] = (gr_or_gi @ ent)^T, tf32
        int p = bx >> 1, which = bx & 1;
        const float* g = (p == 0) ? (which ? giq : grq)
                       : (p == 1) ? (which ? gik : grk)
                                  : (which ? giv : grv);
        const float* e = (p == 0) ? entq : (p == 1) ? entk : entv;
        for (int i = tid; i < 4096; i += 256) { sg[(i>>6)*65 + (i&63)] = g[i]; se[i] = e[i]; }
        __syncthreads();
        for (int idx = tid; idx < 4096; idx += 256) {
            int r = idx >> 6, c = idx & 63;
            float acc = 0.f;
#pragma unroll 8
            for (int k = 0; k < 64; k++) acc = fmaf(sg[r*65 + k], se[k*64 + c], acc);
            g_geT[p][which][c*64 + r] = to_tf32(acc);
        }
    } else if (bx < 14) {
        // g_m2T[h] = ((q_meas[:,h] . w_h) @ interf[h] * 0.125)^T, tf32
        int h = bx - 6;
        for (int i = tid; i < 4096; i += 256) {
            int r = i >> 6, c = i & 63;
            sg[r*65 + c] = qmeas[(size_t)r * ND + h*64 + c] * supw[h*64 + c];
            se[i] = interf[(size_t)h*4096 + i];
        }
        __syncthreads();
        for (int idx = tid; idx < 4096; idx += 256) {
            int r = idx >> 6, c = idx & 63;
            float acc = 0.f;
#pragma unroll 8
            for (int k = 0; k < 64; k++) acc = fmaf(sg[r*65 + k], se[k*64 + c], acc);
            g_m2T[h][c*64 + r] = to_tf32(acc * 0.125f);
        }
    } else if (bx < 17) {
        // encT: [512][64] -> [64][512]
        int p = bx - 14;
        const float* enc = (p == 0) ? qenc : (p == 1) ? kenc : venc;
        for (int kt = 0; kt < 8; kt++)
            transpose_tile(g_encT[p] + kt*64, 512, enc + (size_t)kt*64*64, 64, nullptr, tid, sg);
    } else if (bx < 19) {
        // measT for k,v with sup_w fold: measT[n][k] = meas[k][n]*supw[n]
        int p = bx - 16;   // 1 or 2
        const float* meas = (p == 1) ? kmeas : vmeas;
        for (int ct = 0; ct < 8; ct++)
            transpose_tile(g_measT[p] + (size_t)ct*4096, 64, meas + ct*64, 512, supw + ct*64, tid, sg);
    } else {
        // w_outT: tile (i,j) of w -> tile (j,i) of woT
        int t = bx - 19;   // 0..63
        int i = t >> 3, j = t & 7;
        transpose_tile(g_woT + (size_t)(j*64)*512 + i*64, 512,
                       wout + (size_t)(i*64)*512 + j*64, 512, nullptr, tid, sg);
    }
}

// ---------------------------------------------------------------------------
// Kernel 2: fused QNL via tf32 MMA. p==0 output IS qm (M2 folds meas.w@interf/8);
// p==1/2 have sup_w folded into measT. All stores tf32.
// ---------------------------------------------------------------------------
__global__ void __launch_bounds__(256) k_qnl(const float* __restrict__ x) {
    const int p  = blockIdx.x / (NBS/64);
    const int rt = blockIdx.x % (NBS/64);

    __shared__ float sA[64*LDA];
    __shared__ float sB[64*LDA];
    const int tid  = threadIdx.x;
    const int lane = tid & 31;
    const int warp = tid >> 5;
    const int wr = (warp >> 1) << 4;
    const int wc = (warp & 1) << 5;
    const int g4 = lane >> 2;
    const int l4 = lane & 3;
    const int r0 = rt * 64;

    // phase 1: XE = X_tile @ enc  (B = encT)
    float xe[4][4];
#pragma unroll
    for (int ns = 0; ns < 4; ns++)
#pragma unroll
        for (int j = 0; j < 4; j++) xe[ns][j] = 0.f;
    for (int kt = 0; kt < 8; kt++) {
        ld_tile_cvt(sA, x + (size_t)r0*ND + kt*64, ND, tid);
        ld_tile    (sB, g_encT[p] + kt*64, 512, tid);
        __syncthreads();
        gemm64_acc(xe, sA, sB, wr, wc, g4, l4);
        __syncthreads();
    }
    frag_to_smem(sA, xe, wr, wc, g4, l4);
    __syncthreads();

    // phase 2: er = XE@GRE, ei = XE@GIE, prob = er^2+ei^2
    ld_tile(sB, g_geT[p][0], 64, tid);
    __syncthreads();
    float er[4][4];
#pragma unroll
    for (int ns = 0; ns < 4; ns++)
#pragma unroll
        for (int j = 0; j < 4; j++) er[ns][j] = 0.f;
    gemm64_acc(er, sA, sB, wr, wc, g4, l4);
    __syncthreads();
    ld_tile(sB, g_geT[p][1], 64, tid);
    __syncthreads();
    float ei[4][4];
#pragma unroll
    for (int ns = 0; ns < 4; ns++)
#pragma unroll
        for (int j = 0; j < 4; j++) ei[ns][j] = 0.f;
    gemm64_acc(ei, sA, sB, wr, wc, g4, l4);
#pragma unroll
    for (int ns = 0; ns < 4; ns++)
#pragma unroll
        for (int j = 0; j < 4; j++) er[ns][j] = er[ns][j]*er[ns][j] + ei[ns][j]*ei[ns][j];
    __syncthreads();
    frag_to_smem(sA, er, wr, wc, g4, l4);
    __syncthreads();

    // phase 3: out = prob @ (M2T or measT), write (b,h,s,d)
    const int b  = r0 >> 11;
    const int s0 = r0 & 2047;
    for (int ct = 0; ct < 8; ct++) {
        const float* bsrc = (p == 0) ? g_m2T[ct] : (g_measT[p] + (size_t)ct*4096);
        ld_tile(sB, bsrc, 64, tid);
        __syncthreads();
        float o[4][4];
#pragma unroll
        for (int ns = 0; ns < 4; ns++)
#pragma unroll
            for (int j = 0; j < 4; j++) o[ns][j] = 0.f;
        gemm64_acc(o, sA, sB, wr, wc, g4, l4);
        float* outp = g_qkv[p] + ((size_t)(b*NH + ct)*NS + s0) * NHD;
#pragma unroll
        for (int ns = 0; ns < 4; ns++) {
            int c = wc + ns*8 + 2*l4;
            int r = wr + g4;
            outp[(size_t)r*64 + c]       = to_tf32(o[ns][0]);
            outp[(size_t)r*64 + c + 1]   = to_tf32(o[ns][1]);
            outp[(size_t)(r+8)*64 + c]   = to_tf32(o[ns][2]);
            outp[(size_t)(r+8)*64 + c+1] = to_tf32(o[ns][3]);
        }
        __syncthreads();
    }
}

// ---------------------------------------------------------------------------
// Kernel 3: flash attention via mma.sync m16n8k8 tf32, 64x64 tiles. (unchanged)
// ---------------------------------------------------------------------------
#define ATT_SMEM_FLOATS (3*64*LDQ + 64*LDV + 128)

#define EXP16_ONE(vv) do {                         \
    float t = to_tf32(__expf((vv) - mnew));        \
    (vv) = t; sum += t; } while (0)

__global__ void __launch_bounds__(256) k_attn() {
    extern __shared__ float sm[];
    float* sQ = sm;
    float* sK = sQ + 64*LDQ;
    float* sS = sK + 64*LDQ;
    float* sV = sS + 64*LDQ;
    float* sc = sV + 64*LDV;
    float* sl = sc + 64;

    const int tid  = threadIdx.x;
    const int lane = tid & 31;
    const int warp = tid >> 5;
    const int bh = blockIdx.x >> 5;
    const int qt = blockIdx.x & 31;
    const int wr = (warp >> 1) << 4;
    const int wc = (warp & 1) << 5;
    const int g4 = lane >> 2;
    const int l4 = lane & 3;
    const int srow = tid >> 2;
    const int sseg = (tid & 3) << 4;

    load_tile_s(sQ, LDQ, g_qkv[0] + ((size_t)bh*NS + qt*64)*NHD, tid);

    float o[4][4];
#pragma unroll
    for (int ds = 0; ds < 4; ds++)
#pragma unroll
        for (int j = 0; j < 4; j++) o[ds][j] = 0.f;
    float mrow = -1e30f, lrow = 0.f;

    for (int jt = 0; jt < NS/64; jt++) {
        load_tile_s(sK, LDQ, g_qkv[1] + ((size_t)bh*NS + jt*64)*NHD, tid);
        load_tile_s(sV, LDV, g_qkv[2] + ((size_t)bh*NS + jt*64)*NHD, tid);
        __syncthreads();

        float sf[4][4];
#pragma unroll
        for (int ns = 0; ns < 4; ns++)
#pragma unroll
            for (int j = 0; j < 4; j++) sf[ns][j] = 0.f;
#pragma unroll
        for (int kk = 0; kk < 8; kk++) {
            uint32_t a[4];
            const float* qp = sQ + (wr + g4)*LDQ + kk*8 + l4;
            a[0] = fbits(qp[0]);       a[1] = fbits(qp[8*LDQ]);
            a[2] = fbits(qp[4]);       a[3] = fbits(qp[8*LDQ + 4]);
#pragma unroll
            for (int ns = 0; ns < 4; ns++) {
                const float* kp = sK + (wc + ns*8 + g4)*LDQ + kk*8 + l4;
                uint32_t b[2] = { fbits(kp[0]), fbits(kp[4]) };
                mma_tf32(sf[ns], a, b, sf[ns]);
            }
        }
#pragma unroll
        for (int ns = 0; ns < 4; ns++) {
            float* sp = sS + (wr + g4)*LDQ + wc + ns*8 + 2*l4;
            sp[0] = sf[ns][0]; sp[1] = sf[ns][1];
            sp[8*LDQ] = sf[ns][2]; sp[8*LDQ + 1] = sf[ns][3];
        }
        __syncthreads();

        {
            float* rp = sS + srow*LDQ + sseg;
            float4 v0 = *reinterpret_cast<float4*>(rp + 0);
            float4 v1 = *reinterpret_cast<float4*>(rp + 4);
            float4 v2 = *reinterpret_cast<float4*>(rp + 8);
            float4 v3 = *reinterpret_cast<float4*>(rp + 12);
            float mx = fmaxf(fmaxf(fmaxf(v0.x, v0.y), fmaxf(v0.z, v0.w)),
                             fmaxf(fmaxf(v1.x, v1.y), fmaxf(v1.z, v1.w)));
            mx = fmaxf(mx, fmaxf(fmaxf(fmaxf(v2.x, v2.y), fmaxf(v2.z, v2.w)),
                                 fmaxf(fmaxf(v3.x, v3.y), fmaxf(v3.z, v3.w))));
            mx = fmaxf(mx, __shfl_xor_sync(0xffffffffu, mx, 1));
            mx = fmaxf(mx, __shfl_xor_sync(0xffffffffu, mx, 2));
            float mnew = fmaxf(mrow, mx);
            float corr = __expf(mrow - mnew);
            float sum = 0.f;
            EXP16_ONE(v0.x); EXP16_ONE(v0.y); EXP16_ONE(v0.z); EXP16_ONE(v0.w);
            EXP16_ONE(v1.x); EXP16_ONE(v1.y); EXP16_ONE(v1.z); EXP16_ONE(v1.w);
            EXP16_ONE(v2.x); EXP16_ONE(v2.y); EXP16_ONE(v2.z); EXP16_ONE(v2.w);
            EXP16_ONE(v3.x); EXP16_ONE(v3.y); EXP16_ONE(v3.z); EXP16_ONE(v3.w);
            sum += __shfl_xor_sync(0xffffffffu, sum, 1);
            sum += __shfl_xor_sync(0xffffffffu, sum, 2);
            lrow = lrow * corr + sum;
            mrow = mnew;
            *reinterpret_cast<float4*>(rp + 0)  = v0;
            *reinterpret_cast<float4*>(rp + 4)  = v1;
            *reinterpret_cast<float4*>(rp + 8)  = v2;
            *reinterpret_cast<float4*>(rp + 12) = v3;
            if ((tid & 3) == 0) sc[srow] = corr;
        }
        __syncthreads();

        float cf0 = sc[wr + g4], cf1 = sc[wr + g4 + 8];
#pragma unroll
        for (int ds = 0; ds < 4; ds++) {
            o[ds][0] *= cf0; o[ds][1] *= cf0;
            o[ds][2] *= cf1; o[ds][3] *= cf1;
        }
#pragma unroll
        for (int kk = 0; kk < 8; kk++) {
            uint32_t a[4];
            const float* pp = sS + (wr + g4)*LDQ + kk*8 + l4;
            a[0] = fbits(pp[0]);       a[1] = fbits(pp[8*LDQ]);
            a[2] = fbits(pp[4]);       a[3] = fbits(pp[8*LDQ + 4]);
#pragma unroll
            for (int ds = 0; ds < 4; ds++) {
                const float* vp = sV + (kk*8 + l4)*LDV + wc + ds*8 + g4;
                uint32_t b[2] = { fbits(vp[0]), fbits(vp[4*LDV]) };
                mma_tf32(o[ds], a, b, o[ds]);
            }
        }
        __syncthreads();
    }

    if ((tid & 3) == 0) sl[srow] = lrow;
    __syncthreads();

    const float inv0 = 1.f / sl[wr + g4];
    const float inv1 = 1.f / sl[wr + g4 + 8];
    const int b = bh >> 3, h = bh & 7;
    const int r0 = qt*64 + wr + g4;
    float* base = g_ao + ((size_t)b*NS + r0)*ND + h*64 + wc;
#pragma unroll
    for (int ds = 0; ds < 4; ds++) {
        int c = ds*8 + 2*l4;
        base[c]            = o[ds][0] * inv0;
        base[c + 1]        = o[ds][1] * inv0;
        base[8*ND + c]     = o[ds][2] * inv1;
        base[8*ND + c + 1] = o[ds][3] * inv1;
    }
}

// ---------------------------------------------------------------------------
// Kernel 4: final projection via tf32 MMA: out = g_ao @ w_out + b_out
// ---------------------------------------------------------------------------
__global__ void __launch_bounds__(256) k_proj(const float* __restrict__ bias,
                                              float* __restrict__ out) {
    const int rt = blockIdx.x;
    const int ct = blockIdx.y;
    __shared__ float sA[64*LDA];
    __shared__ float sB[64*LDA];
    const int tid  = threadIdx.x;
    const int lane = tid & 31;
    const int warp = tid >> 5;
    const int wr = (warp >> 1) << 4;
    const int wc = (warp & 1) << 5;
    const int g4 = lane >> 2;
    const int l4 = lane & 3;
    const int r0 = rt * 64;

    float o[4][4];
#pragma unroll
    for (int ns = 0; ns < 4; ns++)
#pragma unroll
        for (int j = 0; j < 4; j++) o[ns][j] = 0.f;

    for (int kt = 0; kt < 8; kt++) {
        ld_tile_cvt(sA, g_ao + (size_t)r0*ND + kt*64, ND, tid);
        ld_tile    (sB, g_woT + (size_t)(ct*64)*512 + kt*64, 512, tid);
        __syncthreads();
        gemm64_acc(o, sA, sB, wr, wc, g4, l4);
        __syncthreads();
    }

    const int gr_ = r0 + wr + g4;
#pragma unroll
    for (int ns = 0; ns < 4; ns++) {
        int c = ct*64 + wc + ns*8 + 2*l4;
        out[(size_t)gr_*ND + c]       = o[ns][0] + bias[c];
        out[(size_t)gr_*ND + c + 1]   = o[ns][1] + bias[c + 1];
        out[(size_t)(gr_+8)*ND + c]   = o[ns][2] + bias[c];
        out[(size_t)(gr_+8)*ND + c+1] = o[ns][3] + bias[c + 1];
    }
}

// ---------------------------------------------------------------------------
extern "C" void kernel_launch(void* const* d_in, const int* in_sizes, int n_in,
                              void* d_out, int out_size) {
    const float* x      = (const float*)d_in[0];
    const float* q_enc  = (const float*)d_in[1];
    const float* q_gr   = (const float*)d_in[2];
    const float* q_gi   = (const float*)d_in[3];
    const float* q_ent  = (const float*)d_in[4];
    const float* q_meas = (const float*)d_in[5];
    const float* k_enc  = (const float*)d_in[6];
    const float* k_gr   = (const float*)d_in[7];
    const float* k_gi   = (const float*)d_in[8];
    const float* k_ent  = (const float*)d_in[9];
    const float* k_meas = (const float*)d_in[10];
    const float* v_enc  = (const float*)d_in[11];
    const float* v_gr   = (const float*)d_in[12];
    const float* v_gi   = (const float*)d_in[13];
    const float* v_ent  = (const float*)d_in[14];
    const float* v_meas = (const float*)d_in[15];
    const float* sup_w  = (const float*)d_in[16];
    const float* interf = (const float*)d_in[17];
    const float* w_out  = (const float*)d_in[18];
    const float* b_out  = (const float*)d_in[19];
    float* out = (float*)d_out;

    static const int ATT_SMEM = ATT_SMEM_FLOATS * (int)sizeof(float);  // 71168 B
    cudaFuncSetAttribute(k_attn, cudaFuncAttributeMaxDynamicSharedMemorySize, ATT_SMEM);

    k_prep<<<83, 256>>>(q_gr, q_gi, q_ent, k_gr, k_gi, k_ent, v_gr, v_gi, v_ent,
                        q_meas, k_meas, v_meas, q_enc, k_enc, v_enc,
                        sup_w, interf, w_out);
    k_qnl<<<3 * (NBS/64), 256>>>(x);
    k_attn<<<NB*NH*(NS/64), 256, ATT_SMEM>>>();
    k_proj<<<dim3(NBS/64, ND/64), 256>>>(b_out, out);
}

// round 5
// speedup vs baseline: 3.0330x; 1.1820x over previous
#include <cuda_runtime.h>
#include <cstdint>

// Problem constants
#define NB   2
#define NS   2048
#define ND   512
#define NH   8
#define NQ   64
#define NHD  64
#define NBS  (NB*NS)             // 4096 tokens
#define QKV_ELEMS (NB*NH*NS*NHD) // 2,097,152

// Scratch (device globals; no allocations allowed)
__device__ float g_geT[3][2][NQ*NQ];     // (gr@ent)^T per projection, tf32
__device__ float g_m2T[NH][NQ*NHD];      // ((q_meas.h w_h)@interf_h/8)^T, tf32
__device__ float g_encT[3][NQ*ND];       // enc^T [64][512], tf32
__device__ float g_measT[3][ND*NQ];      // meas^T [512][64], w folded (p=1,2), tf32
__device__ float g_woT[ND*ND];           // w_out^T [512][512], tf32
__device__ float g_qkv[3][QKV_ELEMS];    // qm / ks / vs in (b,h,s,d), tf32-rounded
__device__ float g_ao[NBS*ND];           // attention out, (b,s,D)

// ---------------------------------------------------------------------------
// helpers
// ---------------------------------------------------------------------------
__device__ __forceinline__ uint32_t fbits(float x) { return __float_as_uint(x); }

__device__ __forceinline__ float to_tf32(float x) {
    float r;
    asm("cvt.rna.tf32.f32 %0, %1;" : "=f"(r) : "f"(x));
    return r;
}

__device__ __forceinline__ void mma_tf32(float d[4], const uint32_t a[4],
                                         const uint32_t b[2], const float c[4]) {
    asm volatile("mma.sync.aligned.m16n8k8.row.col.f32.tf32.tf32.f32 "
                 "{%0,%1,%2,%3}, {%4,%5,%6,%7}, {%8,%9}, {%10,%11,%12,%13};"
                 : "=f"(d[0]), "=f"(d[1]), "=f"(d[2]), "=f"(d[3])
                 : "r"(a[0]), "r"(a[1]), "r"(a[2]), "r"(a[3]),
                   "r"(b[0]), "r"(b[1]),
                   "f"(c[0]), "f"(c[1]), "f"(c[2]), "f"(c[3]));
}

#define LDA 68   // smem stride for MMA GEMM tiles
#define LDQ 68
#define LDV 72

// 64x64 tile load: global (row stride ldg) -> smem (row stride LDA)
__device__ __forceinline__ void ld_tile(float* s, const float* g, int ldg, int tid) {
#pragma unroll
    for (int i = 0; i < 4; i++) {
        int idx = tid + 256 * i;
        int row = idx >> 4;
        int c   = (idx & 15) * 4;
        float4 v = *reinterpret_cast<const float4*>(g + (size_t)row * ldg + c);
        s[row*LDA + c + 0] = v.x;
        s[row*LDA + c + 1] = v.y;
        s[row*LDA + c + 2] = v.z;
        s[row*LDA + c + 3] = v.w;
    }
}

// same, with tf32 rounding of each element
__device__ __forceinline__ void ld_tile_cvt(float* s, const float* g, int ldg, int tid) {
#pragma unroll
    for (int i = 0; i < 4; i++) {
        int idx = tid + 256 * i;
        int row = idx >> 4;
        int c   = (idx & 15) * 4;
        float4 v = *reinterpret_cast<const float4*>(g + (size_t)row * ldg + c);
        s[row*LDA + c + 0] = to_tf32(v.x);
        s[row*LDA + c + 1] = to_tf32(v.y);
        s[row*LDA + c + 2] = to_tf32(v.z);
        s[row*LDA + c + 3] = to_tf32(v.w);
    }
}

// nrows x 64 tile load, global contiguous, smem stride lds
template<int NROWS>
__device__ __forceinline__ void load_rows(float* s, int lds, const float* g, int tid) {
#pragma unroll
    for (int i = 0; i < NROWS/16; i++) {
        int idx = tid + 256 * i;
        float4 v = reinterpret_cast<const float4*>(g)[idx];
        int row = idx >> 4;
        int c   = (idx & 15) * 4;
        s[row*lds + c + 0] = v.x;
        s[row*lds + c + 1] = v.y;
        s[row*lds + c + 2] = v.z;
        s[row*lds + c + 3] = v.w;
    }
}

// 64x64 MMA GEMM: C(16x32 per warp) += A[m][k]*B[n][k], both stride LDA
__device__ __forceinline__ void gemm64_acc(float (&sf)[4][4], const float* sA, const float* sB,
                                           int wr, int wc, int g4, int l4) {
#pragma unroll
    for (int kk = 0; kk < 8; kk++) {
        uint32_t a[4];
        const float* ap = sA + (wr + g4)*LDA + kk*8 + l4;
        a[0] = fbits(ap[0]);       a[1] = fbits(ap[8*LDA]);
        a[2] = fbits(ap[4]);       a[3] = fbits(ap[8*LDA + 4]);
#pragma unroll
        for (int ns = 0; ns < 4; ns++) {
            const float* bp = sB + (wc + ns*8 + g4)*LDA + kk*8 + l4;
            uint32_t b[2] = { fbits(bp[0]), fbits(bp[4]) };
            mma_tf32(sf[ns], a, b, sf[ns]);
        }
    }
}

// write C fragments into stride-LDA smem, tf32-rounded
__device__ __forceinline__ void frag_to_smem(float* s, const float (&f)[4][4],
                                             int wr, int wc, int g4, int l4) {
#pragma unroll
    for (int ns = 0; ns < 4; ns++) {
        float* sp = s + (wr + g4)*LDA + wc + ns*8 + 2*l4;
        sp[0] = to_tf32(f[ns][0]); sp[1] = to_tf32(f[ns][1]);
        sp[8*LDA] = to_tf32(f[ns][2]); sp[8*LDA + 1] = to_tf32(f[ns][3]);
    }
}

// ---------------------------------------------------------------------------
// Kernel 1: prep — folded gates (transposed), M2^T, enc^T, meas^T(.w), w_out^T
// ---------------------------------------------------------------------------
__device__ __forceinline__ void transpose_tile(float* dst, int ldd, const float* src, int ldsrc,
                                               const float* rowscale, int tid, float* sg) {
    for (int idx = tid; idx < 4096; idx += 256) {
        int r = idx >> 6, c = idx & 63;
        sg[r*65 + c] = src[(size_t)r*ldsrc + c];
    }
    __syncthreads();
    for (int idx = tid; idx < 4096; idx += 256) {
        int n = idx >> 6, k = idx & 63;
        float v = sg[k*65 + n];
        if (rowscale) v *= rowscale[n];
        dst[(size_t)n*ldd + k] = to_tf32(v);
    }
    __syncthreads();
}

__global__ void k_prep(const float* __restrict__ grq, const float* __restrict__ giq, const float* __restrict__ entq,
                       const float* __restrict__ grk, const float* __restrict__ gik, const float* __restrict__ entk,
                       const float* __restrict__ grv, const float* __restrict__ giv, const float* __restrict__ entv,
                       const float* __restrict__ qmeas, const float* __restrict__ kmeas, const float* __restrict__ vmeas,
                       const float* __restrict__ qenc, const float* __restrict__ kenc, const float* __restrict__ venc,
                       const float* __restrict__ supw, const float* __restrict__ interf,
                       const float* __restrict__ wout) {
    __shared__ float sg[64*65];
    __shared__ float se[64*64];
    const int bx = blockIdx.x;
    const int tid = threadIdx.x;

    if (bx < 6) {
        int p = bx >> 1, which = bx & 1;
        const float* g = (p == 0) ? (which ? giq : grq)
                       : (p == 1) ? (which ? gik : grk)
                                  : (which ? giv : grv);
        const float* e = (p == 0) ? entq : (p == 1) ? entk : entv;
        for (int i = tid; i < 4096; i += 256) { sg[(i>>6)*65 + (i&63)] = g[i]; se[i] = e[i]; }
        __syncthreads();
        for (int idx = tid; idx < 4096; idx += 256) {
            int r = idx >> 6, c = idx & 63;
            float acc = 0.f;
#pragma unroll 8
            for (int k = 0; k < 64; k++) acc = fmaf(sg[r*65 + k], se[k*64 + c], acc);
            g_geT[p][which][c*64 + r] = to_tf32(acc);
        }
    } else if (bx < 14) {
        int h = bx - 6;
        for (int i = tid; i < 4096; i += 256) {
            int r = i >> 6, c = i & 63;
            sg[r*65 + c] = qmeas[(size_t)r * ND + h*64 + c] * supw[h*64 + c];
            se[i] = interf[(size_t)h*4096 + i];
        }
        __syncthreads();
        for (int idx = tid; idx < 4096; idx += 256) {
            int r = idx >> 6, c = idx & 63;
            float acc = 0.f;
#pragma unroll 8
            for (int k = 0; k < 64; k++) acc = fmaf(sg[r*65 + k], se[k*64 + c], acc);
            g_m2T[h][c*64 + r] = to_tf32(acc * 0.125f);
        }
    } else if (bx < 17) {
        int p = bx - 14;
        const float* enc = (p == 0) ? qenc : (p == 1) ? kenc : venc;
        for (int kt = 0; kt < 8; kt++)
            transpose_tile(g_encT[p] + kt*64, 512, enc + (size_t)kt*64*64, 64, nullptr, tid, sg);
    } else if (bx < 19) {
        int p = bx - 16;   // 1 or 2
        const float* meas = (p == 1) ? kmeas : vmeas;
        for (int ct = 0; ct < 8; ct++)
            transpose_tile(g_measT[p] + (size_t)ct*4096, 64, meas + ct*64, 512, supw + ct*64, tid, sg);
    } else {
        int t = bx - 19;   // 0..63
        int i = t >> 3, j = t & 7;
        transpose_tile(g_woT + (size_t)(j*64)*512 + i*64, 512,
                       wout + (size_t)(i*64)*512 + j*64, 512, nullptr, tid, sg);
    }
}

// ---------------------------------------------------------------------------
// Kernel 2: fused QNL via tf32 MMA (unchanged from round 4)
// ---------------------------------------------------------------------------
__global__ void __launch_bounds__(256) k_qnl(const float* __restrict__ x) {
    const int p  = blockIdx.x / (NBS/64);
    const int rt = blockIdx.x % (NBS/64);

    __shared__ float sA[64*LDA];
    __shared__ float sB[64*LDA];
    const int tid  = threadIdx.x;
    const int lane = tid & 31;
    const int warp = tid >> 5;
    const int wr = (warp >> 1) << 4;
    const int wc = (warp & 1) << 5;
    const int g4 = lane >> 2;
    const int l4 = lane & 3;
    const int r0 = rt * 64;

    float xe[4][4];
#pragma unroll
    for (int ns = 0; ns < 4; ns++)
#pragma unroll
        for (int j = 0; j < 4; j++) xe[ns][j] = 0.f;
    for (int kt = 0; kt < 8; kt++) {
        ld_tile_cvt(sA, x + (size_t)r0*ND + kt*64, ND, tid);
        ld_tile    (sB, g_encT[p] + kt*64, 512, tid);
        __syncthreads();
        gemm64_acc(xe, sA, sB, wr, wc, g4, l4);
        __syncthreads();
    }
    frag_to_smem(sA, xe, wr, wc, g4, l4);
    __syncthreads();

    ld_tile(sB, g_geT[p][0], 64, tid);
    __syncthreads();
    float er[4][4];
#pragma unroll
    for (int ns = 0; ns < 4; ns++)
#pragma unroll
        for (int j = 0; j < 4; j++) er[ns][j] = 0.f;
    gemm64_acc(er, sA, sB, wr, wc, g4, l4);
    __syncthreads();
    ld_tile(sB, g_geT[p][1], 64, tid);
    __syncthreads();
    float ei[4][4];
#pragma unroll
    for (int ns = 0; ns < 4; ns++)
#pragma unroll
        for (int j = 0; j < 4; j++) ei[ns][j] = 0.f;
    gemm64_acc(ei, sA, sB, wr, wc, g4, l4);
#pragma unroll
    for (int ns = 0; ns < 4; ns++)
#pragma unroll
        for (int j = 0; j < 4; j++) er[ns][j] = er[ns][j]*er[ns][j] + ei[ns][j]*ei[ns][j];
    __syncthreads();
    frag_to_smem(sA, er, wr, wc, g4, l4);
    __syncthreads();

    const int b  = r0 >> 11;
    const int s0 = r0 & 2047;
    for (int ct = 0; ct < 8; ct++) {
        const float* bsrc = (p == 0) ? g_m2T[ct] : (g_measT[p] + (size_t)ct*4096);
        ld_tile(sB, bsrc, 64, tid);
        __syncthreads();
        float o[4][4];
#pragma unroll
        for (int ns = 0; ns < 4; ns++)
#pragma unroll
            for (int j = 0; j < 4; j++) o[ns][j] = 0.f;
        gemm64_acc(o, sA, sB, wr, wc, g4, l4);
        float* outp = g_qkv[p] + ((size_t)(b*NH + ct)*NS + s0) * NHD;
#pragma unroll
        for (int ns = 0; ns < 4; ns++) {
            int c = wc + ns*8 + 2*l4;
            int r = wr + g4;
            outp[(size_t)r*64 + c]       = to_tf32(o[ns][0]);
            outp[(size_t)r*64 + c + 1]   = to_tf32(o[ns][1]);
            outp[(size_t)(r+8)*64 + c]   = to_tf32(o[ns][2]);
            outp[(size_t)(r+8)*64 + c+1] = to_tf32(o[ns][3]);
        }
        __syncthreads();
    }
}

// ---------------------------------------------------------------------------
// Kernel 3: flash attention, 128 q-rows/CTA, 64-col KV tiles, tf32 MMA.
//  8 warps in 4x2: wr in {0,32,64,96} (32 rows each), wc in {0,32}.
// ---------------------------------------------------------------------------
#define ATT_SMEM_FLOATS (128*LDQ + 64*LDQ + 128*LDQ + 64*LDV + 256)

#define EXP1(vv) do {                              \
    float t = to_tf32(__expf((vv) - mnew));        \
    (vv) = t; sum += t; } while (0)

__global__ void __launch_bounds__(256) k_attn() {
    extern __shared__ float sm[];
    float* sQ = sm;                 // 128 x LDQ
    float* sK = sQ + 128*LDQ;       // 64 x LDQ
    float* sS = sK + 64*LDQ;        // 128 x LDQ
    float* sV = sS + 128*LDQ;       // 64 x LDV
    float* sc = sV + 64*LDV;        // 128 correction factors
    float* sl = sc + 128;           // 128 row sums

    const int tid  = threadIdx.x;
    const int lane = tid & 31;
    const int warp = tid >> 5;
    const int bh = blockIdx.x >> 4;
    const int qt = blockIdx.x & 15;
    const int wr = (warp >> 1) << 5;   // 0,32,64,96
    const int wc = (warp & 1) << 5;    // 0,32
    const int g4 = lane >> 2;
    const int l4 = lane & 3;
    const int srow = tid >> 1;         // softmax row (0..127)
    const int sseg = (tid & 1) << 5;   // 32-col half

    load_rows<128>(sQ, LDQ, g_qkv[0] + ((size_t)bh*NS + qt*128)*NHD, tid);

    // O accumulators: o[g][ds][4], g=row-group (wr+32g? no: +16g), ds=col step
    float o[2][4][4];
#pragma unroll
    for (int g = 0; g < 2; g++)
#pragma unroll
        for (int ds = 0; ds < 4; ds++)
#pragma unroll
            for (int j = 0; j < 4; j++) o[g][ds][j] = 0.f;
    float mrow = -1e30f, lrow = 0.f;

    for (int jt = 0; jt < NS/64; jt++) {
        load_rows<64>(sK, LDQ, g_qkv[1] + ((size_t)bh*NS + jt*64)*NHD, tid);
        load_rows<64>(sV, LDV, g_qkv[2] + ((size_t)bh*NS + jt*64)*NHD, tid);
        __syncthreads();

        // ---- S = Q @ K^T : 32x32 per warp (2 row-groups x 4 n-steps) ----
        float sf[2][4][4];
#pragma unroll
        for (int g = 0; g < 2; g++)
#pragma unroll
            for (int ns = 0; ns < 4; ns++)
#pragma unroll
                for (int j = 0; j < 4; j++) sf[g][ns][j] = 0.f;
#pragma unroll
        for (int kk = 0; kk < 8; kk++) {
            uint32_t a0[4], a1[4];
            const float* qp = sQ + (wr + g4)*LDQ + kk*8 + l4;
            a0[0] = fbits(qp[0]);        a0[1] = fbits(qp[8*LDQ]);
            a0[2] = fbits(qp[4]);        a0[3] = fbits(qp[8*LDQ + 4]);
            const float* qp1 = qp + 16*LDQ;
            a1[0] = fbits(qp1[0]);       a1[1] = fbits(qp1[8*LDQ]);
            a1[2] = fbits(qp1[4]);       a1[3] = fbits(qp1[8*LDQ + 4]);
#pragma unroll
            for (int ns = 0; ns < 4; ns++) {
                const float* kp = sK + (wc + ns*8 + g4)*LDQ + kk*8 + l4;
                uint32_t b[2] = { fbits(kp[0]), fbits(kp[4]) };
                mma_tf32(sf[0][ns], a0, b, sf[0][ns]);
                mma_tf32(sf[1][ns], a1, b, sf[1][ns]);
            }
        }
#pragma unroll
        for (int g = 0; g < 2; g++)
#pragma unroll
            for (int ns = 0; ns < 4; ns++) {
                float* sp = sS + (wr + 16*g + g4)*LDQ + wc + ns*8 + 2*l4;
                sp[0] = sf[g][ns][0]; sp[1] = sf[g][ns][1];
                sp[8*LDQ] = sf[g][ns][2]; sp[8*LDQ + 1] = sf[g][ns][3];
            }
        __syncthreads();

        // ---- online softmax: thread owns 32 cols of one row ----
        {
            float* rp = sS + srow*LDQ + sseg;
            float4 v0 = *reinterpret_cast<float4*>(rp + 0);
            float4 v1 = *reinterpret_cast<float4*>(rp + 4);
            float4 v2 = *reinterpret_cast<float4*>(rp + 8);
            float4 v3 = *reinterpret_cast<float4*>(rp + 12);
            float4 v4 = *reinterpret_cast<float4*>(rp + 16);
            float4 v5 = *reinterpret_cast<float4*>(rp + 20);
            float4 v6 = *reinterpret_cast<float4*>(rp + 24);
            float4 v7 = *reinterpret_cast<float4*>(rp + 28);
            float mx = fmaxf(fmaxf(fmaxf(v0.x, v0.y), fmaxf(v0.z, v0.w)),
                             fmaxf(fmaxf(v1.x, v1.y), fmaxf(v1.z, v1.w)));
            mx = fmaxf(mx, fmaxf(fmaxf(fmaxf(v2.x, v2.y), fmaxf(v2.z, v2.w)),
                                 fmaxf(fmaxf(v3.x, v3.y), fmaxf(v3.z, v3.w))));
            mx = fmaxf(mx, fmaxf(fmaxf(fmaxf(v4.x, v4.y), fmaxf(v4.z, v4.w)),
                                 fmaxf(fmaxf(v5.x, v5.y), fmaxf(v5.z, v5.w))));
            mx = fmaxf(mx, fmaxf(fmaxf(fmaxf(v6.x, v6.y), fmaxf(v6.z, v6.w)),
                                 fmaxf(fmaxf(v7.x, v7.y), fmaxf(v7.z, v7.w))));
            mx = fmaxf(mx, __shfl_xor_sync(0xffffffffu, mx, 1));
            float mnew = fmaxf(mrow, mx);
            float corr = __expf(mrow - mnew);
            float sum = 0.f;
            EXP1(v0.x); EXP1(v0.y); EXP1(v0.z); EXP1(v0.w);
            EXP1(v1.x); EXP1(v1.y); EXP1(v1.z); EXP1(v1.w);
            EXP1(v2.x); EXP1(v2.y); EXP1(v2.z); EXP1(v2.w);
            EXP1(v3.x); EXP1(v3.y); EXP1(v3.z); EXP1(v3.w);
            EXP1(v4.x); EXP1(v4.y); EXP1(v4.z); EXP1(v4.w);
            EXP1(v5.x); EXP1(v5.y); EXP1(v5.z); EXP1(v5.w);
            EXP1(v6.x); EXP1(v6.y); EXP1(v6.z); EXP1(v6.w);
            EXP1(v7.x); EXP1(v7.y); EXP1(v7.z); EXP1(v7.w);
            sum += __shfl_xor_sync(0xffffffffu, sum, 1);
            lrow = lrow * corr + sum;
            mrow = mnew;
            *reinterpret_cast<float4*>(rp + 0)  = v0;
            *reinterpret_cast<float4*>(rp + 4)  = v1;
            *reinterpret_cast<float4*>(rp + 8)  = v2;
            *reinterpret_cast<float4*>(rp + 12) = v3;
            *reinterpret_cast<float4*>(rp + 16) = v4;
            *reinterpret_cast<float4*>(rp + 20) = v5;
            *reinterpret_cast<float4*>(rp + 24) = v6;
            *reinterpret_cast<float4*>(rp + 28) = v7;
            if ((tid & 1) == 0) sc[srow] = corr;
        }
        __syncthreads();

        // ---- rescale O, then O += P @ V ----
#pragma unroll
        for (int g = 0; g < 2; g++) {
            float cf0 = sc[wr + 16*g + g4];
            float cf1 = sc[wr + 16*g + g4 + 8];
#pragma unroll
            for (int ds = 0; ds < 4; ds++) {
                o[g][ds][0] *= cf0; o[g][ds][1] *= cf0;
                o[g][ds][2] *= cf1; o[g][ds][3] *= cf1;
            }
        }
#pragma unroll
        for (int kk = 0; kk < 8; kk++) {
            uint32_t a0[4], a1[4];
            const float* pp = sS + (wr + g4)*LDQ + kk*8 + l4;
            a0[0] = fbits(pp[0]);        a0[1] = fbits(pp[8*LDQ]);
            a0[2] = fbits(pp[4]);        a0[3] = fbits(pp[8*LDQ + 4]);
            const float* pp1 = pp + 16*LDQ;
            a1[0] = fbits(pp1[0]);       a1[1] = fbits(pp1[8*LDQ]);
            a1[2] = fbits(pp1[4]);       a1[3] = fbits(pp1[8*LDQ + 4]);
#pragma unroll
            for (int ds = 0; ds < 4; ds++) {
                const float* vp = sV + (kk*8 + l4)*LDV + wc + ds*8 + g4;
                uint32_t b[2] = { fbits(vp[0]), fbits(vp[4*LDV]) };
                mma_tf32(o[0][ds], a0, b, o[0][ds]);
                mma_tf32(o[1][ds], a1, b, o[1][ds]);
            }
        }
        __syncthreads();
    }

    if ((tid & 1) == 0) sl[srow] = lrow;
    __syncthreads();

    const int b = bh >> 3, h = bh & 7;
    const int r0 = qt*128 + wr;
#pragma unroll
    for (int g = 0; g < 2; g++) {
        const float inv0 = 1.f / sl[wr + 16*g + g4];
        const float inv1 = 1.f / sl[wr + 16*g + g4 + 8];
        float* base = g_ao + ((size_t)b*NS + r0 + 16*g + g4)*ND + h*64 + wc;
#pragma unroll
        for (int ds = 0; ds < 4; ds++) {
            int c = ds*8 + 2*l4;
            base[c]            = o[g][ds][0] * inv0;
            base[c + 1]        = o[g][ds][1] * inv0;
            base[8*ND + c]     = o[g][ds][2] * inv1;
            base[8*ND + c + 1] = o[g][ds][3] * inv1;
        }
    }
}

// ---------------------------------------------------------------------------
// Kernel 4: final projection via tf32 MMA (unchanged)
// ---------------------------------------------------------------------------
__global__ void __launch_bounds__(256) k_proj(const float* __restrict__ bias,
                                              float* __restrict__ out) {
    const int rt = blockIdx.x;
    const int ct = blockIdx.y;
    __shared__ float sA[64*LDA];
    __shared__ float sB[64*LDA];
    const int tid  = threadIdx.x;
    const int lane = tid & 31;
    const int warp = tid >> 5;
    const int wr = (warp >> 1) << 4;
    const int wc = (warp & 1) << 5;
    const int g4 = lane >> 2;
    const int l4 = lane & 3;
    const int r0 = rt * 64;

    float o[4][4];
#pragma unroll
    for (int ns = 0; ns < 4; ns++)
#pragma unroll
        for (int j = 0; j < 4; j++) o[ns][j] = 0.f;

    for (int kt = 0; kt < 8; kt++) {
        ld_tile_cvt(sA, g_ao + (size_t)r0*ND + kt*64, ND, tid);
        ld_tile    (sB, g_woT + (size_t)(ct*64)*512 + kt*64, 512, tid);
        __syncthreads();
        gemm64_acc(o, sA, sB, wr, wc, g4, l4);
        __syncthreads();
    }

    const int gr_ = r0 + wr + g4;
#pragma unroll
    for (int ns = 0; ns < 4; ns++) {
        int c = ct*64 + wc + ns*8 + 2*l4;
        out[(size_t)gr_*ND + c]       = o[ns][0] + bias[c];
        out[(size_t)gr_*ND + c + 1]   = o[ns][1] + bias[c + 1];
        out[(size_t)(gr_+8)*ND + c]   = o[ns][2] + bias[c];
        out[(size_t)(gr_+8)*ND + c+1] = o[ns][3] + bias[c + 1];
    }
}

// ---------------------------------------------------------------------------
extern "C" void kernel_launch(void* const* d_in, const int* in_sizes, int n_in,
                              void* d_out, int out_size) {
    const float* x      = (const float*)d_in[0];
    const float* q_enc  = (const float*)d_in[1];
    const float* q_gr   = (const float*)d_in[2];
    const float* q_gi   = (const float*)d_in[3];
    const float* q_ent  = (const float*)d_in[4];
    const float* q_meas = (const float*)d_in[5];
    const float* k_enc  = (const float*)d_in[6];
    const float* k_gr   = (const float*)d_in[7];
    const float* k_gi   = (const float*)d_in[8];
    const float* k_ent  = (const float*)d_in[9];
    const float* k_meas = (const float*)d_in[10];
    const float* v_enc  = (const float*)d_in[11];
    const float* v_gr   = (const float*)d_in[12];
    const float* v_gi   = (const float*)d_in[13];
    const float* v_ent  = (const float*)d_in[14];
    const float* v_meas = (const float*)d_in[15];
    const float* sup_w  = (const float*)d_in[16];
    const float* interf = (const float*)d_in[17];
    const float* w_out  = (const float*)d_in[18];
    const float* b_out  = (const float*)d_in[19];
    float* out = (float*)d_out;

    static const int ATT_SMEM = ATT_SMEM_FLOATS * (int)sizeof(float);  // 106496 B
    cudaFuncSetAttribute(k_attn, cudaFuncAttributeMaxDynamicSharedMemorySize, ATT_SMEM);

    k_prep<<<83, 256>>>(q_gr, q_gi, q_ent, k_gr, k_gi, k_ent, v_gr, v_gi, v_ent,
                        q_meas, k_meas, v_meas, q_enc, k_enc, v_enc,
                        sup_w, interf, w_out);
    k_qnl<<<3 * (NBS/64), 256>>>(x);
    k_attn<<<NB*NH*(NS/128), 256, ATT_SMEM>>>();
    k_proj<<<dim3(NBS/64, ND/64), 256>>>(b_out, out);
}

// round 6
// speedup vs baseline: 3.6627x; 1.2076x over previous
#include <cuda_runtime.h>
#include <cstdint>

// Problem constants
#define NB   2
#define NS   2048
#define ND   512
#define NH   8
#define NQ   64
#define NHD  64
#define NBS  (NB*NS)             // 4096 tokens
#define QKV_ELEMS (NB*NH*NS*NHD) // 2,097,152

// Scratch (device globals; no allocations allowed)
__device__ float g_geT[3][2][NQ*NQ];     // (gr@ent)^T per projection, tf32
__device__ float g_m2T[NH][NQ*NHD];      // ((q_meas.h w_h)@interf_h/8)^T, tf32
__device__ float g_encT[3][NQ*ND];       // enc^T [64][512], tf32
__device__ float g_measT[3][ND*NQ];      // meas^T [512][64], w folded (p=1,2), tf32
__device__ float g_woT[ND*ND];           // w_out^T [512][512], tf32
__device__ float g_qkv[3][QKV_ELEMS];    // qm / ks / vs in (b,h,s,d), tf32-rounded
__device__ float g_ao[NBS*ND];           // attention out, (b,s,D)

// ---------------------------------------------------------------------------
// helpers
// ---------------------------------------------------------------------------
__device__ __forceinline__ uint32_t fbits(float x) { return __float_as_uint(x); }

__device__ __forceinline__ float to_tf32(float x) {
    float r;
    asm("cvt.rna.tf32.f32 %0, %1;" : "=f"(r) : "f"(x));
    return r;
}

__device__ __forceinline__ void mma_tf32(float d[4], const uint32_t a[4],
                                         const uint32_t b[2], const float c[4]) {
    asm volatile("mma.sync.aligned.m16n8k8.row.col.f32.tf32.tf32.f32 "
                 "{%0,%1,%2,%3}, {%4,%5,%6,%7}, {%8,%9}, {%10,%11,%12,%13};"
                 : "=f"(d[0]), "=f"(d[1]), "=f"(d[2]), "=f"(d[3])
                 : "r"(a[0]), "r"(a[1]), "r"(a[2]), "r"(a[3]),
                   "r"(b[0]), "r"(b[1]),
                   "f"(c[0]), "f"(c[1]), "f"(c[2]), "f"(c[3]));
}

#define LDA 68   // smem stride for MMA GEMM tiles
#define LDK 68
#define LDV 72

#define CP_ASYNC16(dst, src) \
    asm volatile("cp.async.cg.shared.global [%0], [%1], 16;" :: "r"(dst), "l"(src))
#define CP_COMMIT()  asm volatile("cp.async.commit_group;")
#define CP_WAIT0()   asm volatile("cp.async.wait_group 0;")

// 64x64 tile load: global (row stride ldg) -> smem (row stride LDA)
__device__ __forceinline__ void ld_tile(float* s, const float* g, int ldg, int tid) {
#pragma unroll
    for (int i = 0; i < 4; i++) {
        int idx = tid + 256 * i;
        int row = idx >> 4;
        int c   = (idx & 15) * 4;
        float4 v = *reinterpret_cast<const float4*>(g + (size_t)row * ldg + c);
        s[row*LDA + c + 0] = v.x;
        s[row*LDA + c + 1] = v.y;
        s[row*LDA + c + 2] = v.z;
        s[row*LDA + c + 3] = v.w;
    }
}

// same, with tf32 rounding of each element
__device__ __forceinline__ void ld_tile_cvt(float* s, const float* g, int ldg, int tid) {
#pragma unroll
    for (int i = 0; i < 4; i++) {
        int idx = tid + 256 * i;
        int row = idx >> 4;
        int c   = (idx & 15) * 4;
        float4 v = *reinterpret_cast<const float4*>(g + (size_t)row * ldg + c);
        s[row*LDA + c + 0] = to_tf32(v.x);
        s[row*LDA + c + 1] = to_tf32(v.y);
        s[row*LDA + c + 2] = to_tf32(v.z);
        s[row*LDA + c + 3] = to_tf32(v.w);
    }
}

// nrows x 64 tile load, global contiguous, smem stride lds (plain ld/st)
template<int NROWS>
__device__ __forceinline__ void load_rows(float* s, int lds, const float* g, int tid) {
#pragma unroll
    for (int i = 0; i < NROWS/16; i++) {
        int idx = tid + 256 * i;
        float4 v = reinterpret_cast<const float4*>(g)[idx];
        int row = idx >> 4;
        int c   = (idx & 15) * 4;
        s[row*lds + c + 0] = v.x;
        s[row*lds + c + 1] = v.y;
        s[row*lds + c + 2] = v.z;
        s[row*lds + c + 3] = v.w;
    }
}

// async 64x64 tile fill, smem row stride lds (floats)
__device__ __forceinline__ void cpa_tile(uint32_t s_u32, int lds, const float* g, int tid) {
#pragma unroll
    for (int i = 0; i < 4; i++) {
        int idx = tid + 256 * i;
        int row = idx >> 4;
        int c   = (idx & 15) * 4;
        CP_ASYNC16(s_u32 + (uint32_t)(row*lds + c)*4u, g + idx*4);
    }
}

// 64x64 MMA GEMM: C(16x32 per warp) += A[m][k]*B[n][k], both stride LDA
__device__ __forceinline__ void gemm64_acc(float (&sf)[4][4], const float* sA, const float* sB,
                                           int wr, int wc, int g4, int l4) {
#pragma unroll
    for (int kk = 0; kk < 8; kk++) {
        uint32_t a[4];
        const float* ap = sA + (wr + g4)*LDA + kk*8 + l4;
        a[0] = fbits(ap[0]);       a[1] = fbits(ap[8*LDA]);
        a[2] = fbits(ap[4]);       a[3] = fbits(ap[8*LDA + 4]);
#pragma unroll
        for (int ns = 0; ns < 4; ns++) {
            const float* bp = sB + (wc + ns*8 + g4)*LDA + kk*8 + l4;
            uint32_t b[2] = { fbits(bp[0]), fbits(bp[4]) };
            mma_tf32(sf[ns], a, b, sf[ns]);
        }
    }
}

// write C fragments into stride-LDA smem, tf32-rounded
__device__ __forceinline__ void frag_to_smem(float* s, const float (&f)[4][4],
                                             int wr, int wc, int g4, int l4) {
#pragma unroll
    for (int ns = 0; ns < 4; ns++) {
        float* sp = s + (wr + g4)*LDA + wc + ns*8 + 2*l4;
        sp[0] = to_tf32(f[ns][0]); sp[1] = to_tf32(f[ns][1]);
        sp[8*LDA] = to_tf32(f[ns][2]); sp[8*LDA + 1] = to_tf32(f[ns][3]);
    }
}

// ---------------------------------------------------------------------------
// Kernel 1: prep — folded gates (transposed), M2^T, enc^T, meas^T(.w), w_out^T
// ---------------------------------------------------------------------------
__device__ __forceinline__ void transpose_tile(float* dst, int ldd, const float* src, int ldsrc,
                                               const float* rowscale, int tid, float* sg) {
    for (int idx = tid; idx < 4096; idx += 256) {
        int r = idx >> 6, c = idx & 63;
        sg[r*65 + c] = src[(size_t)r*ldsrc + c];
    }
    __syncthreads();
    for (int idx = tid; idx < 4096; idx += 256) {
        int n = idx >> 6, k = idx & 63;
        float v = sg[k*65 + n];
        if (rowscale) v *= rowscale[n];
        dst[(size_t)n*ldd + k] = to_tf32(v);
    }
    __syncthreads();
}

__global__ void k_prep(const float* __restrict__ grq, const float* __restrict__ giq, const float* __restrict__ entq,
                       const float* __restrict__ grk, const float* __restrict__ gik, const float* __restrict__ entk,
                       const float* __restrict__ grv, const float* __restrict__ giv, const float* __restrict__ entv,
                       const float* __restrict__ qmeas, const float* __restrict__ kmeas, const float* __restrict__ vmeas,
                       const float* __restrict__ qenc, const float* __restrict__ kenc, const float* __restrict__ venc,
                       const float* __restrict__ supw, const float* __restrict__ interf,
                       const float* __restrict__ wout) {
    __shared__ float sg[64*65];
    __shared__ float se[64*64];
    const int bx = blockIdx.x;
    const int tid = threadIdx.x;

    if (bx < 6) {
        int p = bx >> 1, which = bx & 1;
        const float* g = (p == 0) ? (which ? giq : grq)
                       : (p == 1) ? (which ? gik : grk)
                                  : (which ? giv : grv);
        const float* e = (p == 0) ? entq : (p == 1) ? entk : entv;
        for (int i = tid; i < 4096; i += 256) { sg[(i>>6)*65 + (i&63)] = g[i]; se[i] = e[i]; }
        __syncthreads();
        for (int idx = tid; idx < 4096; idx += 256) {
            int r = idx >> 6, c = idx & 63;
            float acc = 0.f;
#pragma unroll 8
            for (int k = 0; k < 64; k++) acc = fmaf(sg[r*65 + k], se[k*64 + c], acc);
            g_geT[p][which][c*64 + r] = to_tf32(acc);
        }
    } else if (bx < 14) {
        int h = bx - 6;
        for (int i = tid; i < 4096; i += 256) {
            int r = i >> 6, c = i & 63;
            sg[r*65 + c] = qmeas[(size_t)r * ND + h*64 + c] * supw[h*64 + c];
            se[i] = interf[(size_t)h*4096 + i];
        }
        __syncthreads();
        for (int idx = tid; idx < 4096; idx += 256) {
            int r = idx >> 6, c = idx & 63;
            float acc = 0.f;
#pragma unroll 8
            for (int k = 0; k < 64; k++) acc = fmaf(sg[r*65 + k], se[k*64 + c], acc);
            g_m2T[h][c*64 + r] = to_tf32(acc * 0.125f);
        }
    } else if (bx < 17) {
        int p = bx - 14;
        const float* enc = (p == 0) ? qenc : (p == 1) ? kenc : venc;
        for (int kt = 0; kt < 8; kt++)
            transpose_tile(g_encT[p] + kt*64, 512, enc + (size_t)kt*64*64, 64, nullptr, tid, sg);
    } else if (bx < 19) {
        int p = bx - 16;   // 1 or 2
        const float* meas = (p == 1) ? kmeas : vmeas;
        for (int ct = 0; ct < 8; ct++)
            transpose_tile(g_measT[p] + (size_t)ct*4096, 64, meas + ct*64, 512, supw + ct*64, tid, sg);
    } else {
        int t = bx - 19;   // 0..63
        int i = t >> 3, j = t & 7;
        transpose_tile(g_woT + (size_t)(j*64)*512 + i*64, 512,
                       wout + (size_t)(i*64)*512 + j*64, 512, nullptr, tid, sg);
    }
}

// ---------------------------------------------------------------------------
// Kernel 2: fused QNL via tf32 MMA (unchanged)
// ---------------------------------------------------------------------------
__global__ void __launch_bounds__(256) k_qnl(const float* __restrict__ x) {
    const int p  = blockIdx.x / (NBS/64);
    const int rt = blockIdx.x % (NBS/64);

    __shared__ float sA[64*LDA];
    __shared__ float sB[64*LDA];
    const int tid  = threadIdx.x;
    const int lane = tid & 31;
    const int warp = tid >> 5;
    const int wr = (warp >> 1) << 4;
    const int wc = (warp & 1) << 5;
    const int g4 = lane >> 2;
    const int l4 = lane & 3;
    const int r0 = rt * 64;

    float xe[4][4];
#pragma unroll
    for (int ns = 0; ns < 4; ns++)
#pragma unroll
        for (int j = 0; j < 4; j++) xe[ns][j] = 0.f;
    for (int kt = 0; kt < 8; kt++) {
        ld_tile_cvt(sA, x + (size_t)r0*ND + kt*64, ND, tid);
        ld_tile    (sB, g_encT[p] + kt*64, 512, tid);
        __syncthreads();
        gemm64_acc(xe, sA, sB, wr, wc, g4, l4);
        __syncthreads();
    }
    frag_to_smem(sA, xe, wr, wc, g4, l4);
    __syncthreads();

    ld_tile(sB, g_geT[p][0], 64, tid);
    __syncthreads();
    float er[4][4];
#pragma unroll
    for (int ns = 0; ns < 4; ns++)
#pragma unroll
        for (int j = 0; j < 4; j++) er[ns][j] = 0.f;
    gemm64_acc(er, sA, sB, wr, wc, g4, l4);
    __syncthreads();
    ld_tile(sB, g_geT[p][1], 64, tid);
    __syncthreads();
    float ei[4][4];
#pragma unroll
    for (int ns = 0; ns < 4; ns++)
#pragma unroll
        for (int j = 0; j < 4; j++) ei[ns][j] = 0.f;
    gemm64_acc(ei, sA, sB, wr, wc, g4, l4);
#pragma unroll
    for (int ns = 0; ns < 4; ns++)
#pragma unroll
        for (int j = 0; j < 4; j++) er[ns][j] = er[ns][j]*er[ns][j] + ei[ns][j]*ei[ns][j];
    __syncthreads();
    frag_to_smem(sA, er, wr, wc, g4, l4);
    __syncthreads();

    const int b  = r0 >> 11;
    const int s0 = r0 & 2047;
    for (int ct = 0; ct < 8; ct++) {
        const float* bsrc = (p == 0) ? g_m2T[ct] : (g_measT[p] + (size_t)ct*4096);
        ld_tile(sB, bsrc, 64, tid);
        __syncthreads();
        float o[4][4];
#pragma unroll
        for (int ns = 0; ns < 4; ns++)
#pragma unroll
            for (int j = 0; j < 4; j++) o[ns][j] = 0.f;
        gemm64_acc(o, sA, sB, wr, wc, g4, l4);
        float* outp = g_qkv[p] + ((size_t)(b*NH + ct)*NS + s0) * NHD;
#pragma unroll
        for (int ns = 0; ns < 4; ns++) {
            int c = wc + ns*8 + 2*l4;
            int r = wr + g4;
            outp[(size_t)r*64 + c]       = to_tf32(o[ns][0]);
            outp[(size_t)r*64 + c + 1]   = to_tf32(o[ns][1]);
            outp[(size_t)(r+8)*64 + c]   = to_tf32(o[ns][2]);
            outp[(size_t)(r+8)*64 + c+1] = to_tf32(o[ns][3]);
        }
        __syncthreads();
    }
}

// ---------------------------------------------------------------------------
// Kernel 3: flash attention, FA2-style register-resident.
//  8 warps, each owns 16 q-rows x full 64 cols. Q A-frags persistent in regs,
//  S/P stay in C-fragments (softmax + layout shuffle in registers),
//  K/V double-buffered via cp.async. One __syncthreads per KV tile.
// ---------------------------------------------------------------------------
#define ATT_SMEM_FLOATS (2*64*LDK + 2*64*LDV)

__global__ void __launch_bounds__(256) k_attn() {
    extern __shared__ float sm[];
    float* sK0 = sm;                    // 64 x LDK
    float* sK1 = sm + 64*LDK;           // 64 x LDK (contiguous with sK0)
    float* sV0 = sm + 2*64*LDK;         // 64 x LDV
    float* sV1 = sV0 + 64*LDV;

    const int tid  = threadIdx.x;
    const int lane = tid & 31;
    const int warp = tid >> 5;
    const int bh = blockIdx.x >> 4;
    const int qt = blockIdx.x & 15;
    const int g4 = lane >> 2;
    const int l4 = lane & 3;

    const float* gQ = g_qkv[0] + ((size_t)bh*NS + qt*128)*NHD;
    const float* gK = g_qkv[1] + (size_t)bh*NS*NHD;
    const float* gV = g_qkv[2] + (size_t)bh*NS*NHD;

    // ---- stage Q (128x64) through the K buffers, pick up persistent A-frags
    load_rows<128>(sm, LDK, gQ, tid);
    __syncthreads();
    uint32_t qa[8][4];
    {
        const float* qbase = sm + (warp*16 + g4)*LDK;
#pragma unroll
        for (int kk = 0; kk < 8; kk++) {
            const float* qp = qbase + kk*8 + l4;
            qa[kk][0] = fbits(qp[0]);
            qa[kk][1] = fbits(qp[8*LDK]);
            qa[kk][2] = fbits(qp[4]);
            qa[kk][3] = fbits(qp[8*LDK + 4]);
        }
    }
    __syncthreads();

    const uint32_t sK0u = (uint32_t)__cvta_generic_to_shared(sK0);
    const uint32_t sK1u = (uint32_t)__cvta_generic_to_shared(sK1);
    const uint32_t sV0u = (uint32_t)__cvta_generic_to_shared(sV0);
    const uint32_t sV1u = (uint32_t)__cvta_generic_to_shared(sV1);

    // prefetch tile 0 into buffer 0
    cpa_tile(sK0u, LDK, gK, tid);
    cpa_tile(sV0u, LDV, gV, tid);
    CP_COMMIT();

    float o[8][4];
#pragma unroll
    for (int ds = 0; ds < 8; ds++)
#pragma unroll
        for (int j = 0; j < 4; j++) o[ds][j] = 0.f;
    float m0 = -1e30f, m1 = -1e30f, l0 = 0.f, l1 = 0.f;

    for (int jt = 0; jt < NS/64; jt++) {
        CP_WAIT0();
        __syncthreads();          // tile jt ready in buf jt&1; all warps done with jt-1
        const float* sK = (jt & 1) ? sK1 : sK0;
        const float* sV = (jt & 1) ? sV1 : sV0;
        if (jt + 1 < NS/64) {     // overlap next tile's loads with compute
            cpa_tile((jt & 1) ? sK0u : sK1u, LDK, gK + (jt+1)*64*NHD, tid);
            cpa_tile((jt & 1) ? sV0u : sV1u, LDV, gV + (jt+1)*64*NHD, tid);
            CP_COMMIT();
        }

        // ---- S = Q @ K^T : 16 rows x 64 cols per warp, C-frags sf[8][4] ----
        float sf[8][4];
#pragma unroll
        for (int ns = 0; ns < 8; ns++)
#pragma unroll
            for (int j = 0; j < 4; j++) sf[ns][j] = 0.f;
#pragma unroll
        for (int kk = 0; kk < 8; kk++) {
#pragma unroll
            for (int ns = 0; ns < 8; ns++) {
                const float* kp = sK + (ns*8 + g4)*LDK + kk*8 + l4;
                uint32_t b[2] = { fbits(kp[0]), fbits(kp[4]) };
                mma_tf32(sf[ns], qa[kk], b, sf[ns]);
            }
        }

        // ---- register softmax (rows g4 and g4+8) ----
        float mx0 = sf[0][0], mx1 = sf[0][2];
#pragma unroll
        for (int ns = 0; ns < 8; ns++) {
            mx0 = fmaxf(mx0, fmaxf(sf[ns][0], sf[ns][1]));
            mx1 = fmaxf(mx1, fmaxf(sf[ns][2], sf[ns][3]));
        }
        mx0 = fmaxf(mx0, __shfl_xor_sync(0xffffffffu, mx0, 1));
        mx0 = fmaxf(mx0, __shfl_xor_sync(0xffffffffu, mx0, 2));
        mx1 = fmaxf(mx1, __shfl_xor_sync(0xffffffffu, mx1, 1));
        mx1 = fmaxf(mx1, __shfl_xor_sync(0xffffffffu, mx1, 2));
        float mn0 = fmaxf(m0, mx0), mn1 = fmaxf(m1, mx1);
        float c0 = __expf(m0 - mn0), c1 = __expf(m1 - mn1);
        float s0 = 0.f, s1 = 0.f;
#pragma unroll
        for (int ns = 0; ns < 8; ns++) {
            float e0 = to_tf32(__expf(sf[ns][0] - mn0));
            float e1 = to_tf32(__expf(sf[ns][1] - mn0));
            float e2 = to_tf32(__expf(sf[ns][2] - mn1));
            float e3 = to_tf32(__expf(sf[ns][3] - mn1));
            sf[ns][0] = e0; sf[ns][1] = e1; sf[ns][2] = e2; sf[ns][3] = e3;
            s0 += e0 + e1; s1 += e2 + e3;
        }
        s0 += __shfl_xor_sync(0xffffffffu, s0, 1);
        s0 += __shfl_xor_sync(0xffffffffu, s0, 2);
        s1 += __shfl_xor_sync(0xffffffffu, s1, 1);
        s1 += __shfl_xor_sync(0xffffffffu, s1, 2);
        l0 = l0 * c0 + s0; l1 = l1 * c1 + s1;
        m0 = mn0; m1 = mn1;

        // rescale O
#pragma unroll
        for (int ds = 0; ds < 8; ds++) {
            o[ds][0] *= c0; o[ds][1] *= c0;
            o[ds][2] *= c1; o[ds][3] *= c1;
        }

        // ---- O += P @ V : convert P C-layout -> A-layout via quad shuffles ----
        const int qbase2 = lane & ~3;
        const int srcA = qbase2 + (l4 >> 1);
        const int srcB = srcA + 2;
        const bool odd = (l4 & 1);
#pragma unroll
        for (int kk = 0; kk < 8; kk++) {
            float p0 = __shfl_sync(0xffffffffu, sf[kk][0], srcA);
            float p1 = __shfl_sync(0xffffffffu, sf[kk][1], srcA);
            float p2 = __shfl_sync(0xffffffffu, sf[kk][2], srcA);
            float p3 = __shfl_sync(0xffffffffu, sf[kk][3], srcA);
            float r0 = __shfl_sync(0xffffffffu, sf[kk][0], srcB);
            float r1 = __shfl_sync(0xffffffffu, sf[kk][1], srcB);
            float r2 = __shfl_sync(0xffffffffu, sf[kk][2], srcB);
            float r3 = __shfl_sync(0xffffffffu, sf[kk][3], srcB);
            uint32_t a[4];
            a[0] = fbits(odd ? p1 : p0);
            a[1] = fbits(odd ? p3 : p2);
            a[2] = fbits(odd ? r1 : r0);
            a[3] = fbits(odd ? r3 : r2);
#pragma unroll
            for (int ds = 0; ds < 8; ds++) {
                const float* vp = sV + (kk*8 + l4)*LDV + ds*8 + g4;
                uint32_t b[2] = { fbits(vp[0]), fbits(vp[4*LDV]) };
                mma_tf32(o[ds], a, b, o[ds]);
            }
        }
    }

    // ---- epilogue ----
    const float inv0 = 1.f / l0;
    const float inv1 = 1.f / l1;
    const int b = bh >> 3, h = bh & 7;
    const int row0 = qt*128 + warp*16 + g4;
    float* base0 = g_ao + ((size_t)b*NS + row0)*ND + h*64;
    float* base1 = base0 + (size_t)8*ND;
#pragma unroll
    for (int ds = 0; ds < 8; ds++) {
        int c = ds*8 + 2*l4;
        *reinterpret_cast<float2*>(base0 + c) = make_float2(o[ds][0]*inv0, o[ds][1]*inv0);
        *reinterpret_cast<float2*>(base1 + c) = make_float2(o[ds][2]*inv1, o[ds][3]*inv1);
    }
}

// ---------------------------------------------------------------------------
// Kernel 4: final projection via tf32 MMA (unchanged)
// ---------------------------------------------------------------------------
__global__ void __launch_bounds__(256) k_proj(const float* __restrict__ bias,
                                              float* __restrict__ out) {
    const int rt = blockIdx.x;
    const int ct = blockIdx.y;
    __shared__ float sA[64*LDA];
    __shared__ float sB[64*LDA];
    const int tid  = threadIdx.x;
    const int lane = tid & 31;
    const int warp = tid >> 5;
    const int wr = (warp >> 1) << 4;
    const int wc = (warp & 1) << 5;
    const int g4 = lane >> 2;
    const int l4 = lane & 3;
    const int r0 = rt * 64;

    float o[4][4];
#pragma unroll
    for (int ns = 0; ns < 4; ns++)
#pragma unroll
        for (int j = 0; j < 4; j++) o[ns][j] = 0.f;

    for (int kt = 0; kt < 8; kt++) {
        ld_tile_cvt(sA, g_ao + (size_t)r0*ND + kt*64, ND, tid);
        ld_tile    (sB, g_woT + (size_t)(ct*64)*512 + kt*64, 512, tid);
        __syncthreads();
        gemm64_acc(o, sA, sB, wr, wc, g4, l4);
        __syncthreads();
    }

    const int gr_ = r0 + wr + g4;
#pragma unroll
    for (int ns = 0; ns < 4; ns++) {
        int c = ct*64 + wc + ns*8 + 2*l4;
        out[(size_t)gr_*ND + c]       = o[ns][0] + bias[c];
        out[(size_t)gr_*ND + c + 1]   = o[ns][1] + bias[c + 1];
        out[(size_t)(gr_+8)*ND + c]   = o[ns][2] + bias[c];
        out[(size_t)(gr_+8)*ND + c+1] = o[ns][3] + bias[c + 1];
    }
}

// ---------------------------------------------------------------------------
extern "C" void kernel_launch(void* const* d_in, const int* in_sizes, int n_in,
                              void* d_out, int out_size) {
    const float* x      = (const float*)d_in[0];
    const float* q_enc  = (const float*)d_in[1];
    const float* q_gr   = (const float*)d_in[2];
    const float* q_gi   = (const float*)d_in[3];
    const float* q_ent  = (const float*)d_in[4];
    const float* q_meas = (const float*)d_in[5];
    const float* k_enc  = (const float*)d_in[6];
    const float* k_gr   = (const float*)d_in[7];
    const float* k_gi   = (const float*)d_in[8];
    const float* k_ent  = (const float*)d_in[9];
    const float* k_meas = (const float*)d_in[10];
    const float* v_enc  = (const float*)d_in[11];
    const float* v_gr   = (const float*)d_in[12];
    const float* v_gi   = (const float*)d_in[13];
    const float* v_ent  = (const float*)d_in[14];
    const float* v_meas = (const float*)d_in[15];
    const float* sup_w  = (const float*)d_in[16];
    const float* interf = (const float*)d_in[17];
    const float* w_out  = (const float*)d_in[18];
    const float* b_out  = (const float*)d_in[19];
    float* out = (float*)d_out;

    static const int ATT_SMEM = ATT_SMEM_FLOATS * (int)sizeof(float);  // 71680 B
    cudaFuncSetAttribute(k_attn, cudaFuncAttributeMaxDynamicSharedMemorySize, ATT_SMEM);

    k_prep<<<83, 256>>>(q_gr, q_gi, q_ent, k_gr, k_gi, k_ent, v_gr, v_gi, v_ent,
                        q_meas, k_meas, v_meas, q_enc, k_enc, v_enc,
                        sup_w, interf, w_out);
    k_qnl<<<3 * (NBS/64), 256>>>(x);
    k_attn<<<NB*NH*(NS/128), 256, ATT_SMEM>>>();
    k_proj<<<dim3(NBS/64, ND/64), 256>>>(b_out, out);
}